// round 3
// baseline (speedup 1.0000x reference)
#include <cuda_runtime.h>
#include <math.h>
#include <math_constants.h>

#define NN    50000
#define EE    800000
#define DIN   128
#define DH    128
#define DOUTC 40
#define NB    ((NN + 255) / 256)   // 196 scan blocks

// ---------------- device scratch (no allocs allowed) ----------------
__device__ float  g_h [NN*DH];    // h' = (x@W) * dinv[row]
__device__ float  g_x1[NN*DH];    // layer output ping
__device__ float  g_x2[NN*DH];    // layer output pong
__device__ float  g_dinv[NN];
__device__ int    g_deg[NN];
__device__ int    g_rowptr[NN+1];
__device__ int    g_cursor[NN];
__device__ int    g_srcs[EE];     // edge srcs sorted by dst (CSR)
__device__ int    g_bsum[NB];
__device__ int    g_boff[NB];
__device__ float2 g_wd0[DIN*DH];  // W0 duplicated pairs
__device__ float2 g_wd1[DH*DH];   // W1 duplicated pairs
__device__ float2 g_wd2[DH*64];   // W2 duplicated, padded 40->64 cols

// ---------------- f32x2 helpers ----------------
__device__ __forceinline__ unsigned long long pk2(float lo, float hi) {
    unsigned long long r;
    asm("mov.b64 %0, {%1, %2};" : "=l"(r) : "f"(lo), "f"(hi));
    return r;
}
__device__ __forceinline__ void fma2(unsigned long long& d, unsigned long long a,
                                     unsigned long long b) {
    asm("fma.rn.f32x2 %0, %1, %2, %3;" : "=l"(d) : "l"(a), "l"(b), "l"(d));
}
__device__ __forceinline__ float2 upk2(unsigned long long v) {
    float2 f;
    asm("mov.b64 {%0, %1}, %2;" : "=f"(f.x), "=f"(f.y) : "l"(v));
    return f;
}

// ---------------- preprocessing: CSR build ----------------
__global__ void zero_deg_k() {
    int i = blockIdx.x*blockDim.x + threadIdx.x;
    if (i < NN) g_deg[i] = 0;
}

// edge_index is int32 (JAX x64 disabled): [0:EE)=src, [EE:2EE)=dst
__global__ void count_deg_k(const int* __restrict__ ei) {
    int e = blockIdx.x*blockDim.x + threadIdx.x;
    if (e < EE) {
        unsigned d = (unsigned)ei[EE + e];
        if (d < NN) atomicAdd(&g_deg[d], 1);
    }
}

// phase 1: per-block degree sums
__global__ void scan1_k() {
    __shared__ int sd[256];
    int i = blockIdx.x*256 + threadIdx.x;
    sd[threadIdx.x] = (i < NN) ? g_deg[i] : 0;
    __syncthreads();
    for (int off = 128; off; off >>= 1) {
        if (threadIdx.x < off) sd[threadIdx.x] += sd[threadIdx.x + off];
        __syncthreads();
    }
    if (threadIdx.x == 0) g_bsum[blockIdx.x] = sd[0];
}

// phase 2: single block scans NB block sums
__global__ void scan2_k() {
    __shared__ int sd[256];
    int tid = threadIdx.x;
    int v = (tid < NB) ? g_bsum[tid] : 0;
    sd[tid] = v;
    __syncthreads();
    for (int off = 1; off < 256; off <<= 1) {
        int t = (tid >= off) ? sd[tid - off] : 0;
        __syncthreads();
        sd[tid] += t;
        __syncthreads();
    }
    if (tid < NB) g_boff[tid] = sd[tid] - v;       // exclusive
    if (tid == 255) g_rowptr[NN] = sd[255];
}

// phase 3: per-block exclusive scan + write rowptr/cursor/dinv
__global__ void scan3_k() {
    __shared__ int sd[256];
    int tid = threadIdx.x;
    int i = blockIdx.x*256 + tid;
    int d = (i < NN) ? g_deg[i] : 0;
    sd[tid] = d;
    __syncthreads();
    for (int off = 1; off < 256; off <<= 1) {
        int t = (tid >= off) ? sd[tid - off] : 0;
        __syncthreads();
        sd[tid] += t;
        __syncthreads();
    }
    if (i < NN) {
        int base = g_boff[blockIdx.x] + sd[tid] - d;   // exclusive
        g_rowptr[i] = base;
        g_cursor[i] = base;
        g_dinv[i]   = rsqrtf((float)(d + 1));          // +1 self-loop
    }
}

__global__ void sort_edges_k(const int* __restrict__ ei) {
    int e = blockIdx.x*blockDim.x + threadIdx.x;
    if (e < EE) {
        unsigned d = (unsigned)ei[EE + e];
        unsigned s = (unsigned)ei[e];
        if (d < NN && s < NN) {
            int pos = atomicAdd(&g_cursor[d], 1);
            if (pos < EE) g_srcs[pos] = (int)s;
        }
    }
}

// ---------------- W duplication: Wdup[k][c] = (w, w), zero-padded ----------------
__global__ void dupw_k(const float* __restrict__ W, float2* __restrict__ out,
                       int ncIn, int ncPad) {
    int idx = blockIdx.x*blockDim.x + threadIdx.x;
    int tot = DIN * ncPad;
    if (idx < tot) {
        int k = idx / ncPad, c = idx % ncPad;
        float w = (c < ncIn) ? W[k*ncIn + c] : 0.f;
        out[idx] = make_float2(w, w);
    }
}

// ---------------- GEMM: H = (X @ W) * dinv[row], f32x2 packed ----------------
// 256 threads, 64 rows/block. Thread: 8 rows (4 row-pairs) x NCT cols.
// NC = padded col count (128 or 64); NCT = NC/32. ncOut = true output stride.
// SRCSEL: 0 = external ptr, 1 = g_x1, 2 = g_x2. Output always g_h.
template<int NC, int SRCSEL>
__global__ void __launch_bounds__(256) gemm2_k(const float* __restrict__ Xp,
                                               const float2* __restrict__ Wd,
                                               int ncOut) {
    const int NCT = NC / 32;
    const float* X = (SRCSEL == 0) ? Xp : (SRCSEL == 1 ? (const float*)g_x1
                                                       : (const float*)g_x2);
    __shared__ float xs[64][DIN];            // 32 KB
    int tid  = threadIdx.x;
    int row0 = blockIdx.x * 64;

    const float4* Xv = (const float4*)(X + (size_t)row0 * DIN);
    float4* xsv = (float4*)&xs[0][0];
    #pragma unroll
    for (int i = 0; i < 8; i++) {
        int idx = tid + i * 256;             // 0..2047 float4
        int r = idx >> 5;
        xsv[idx] = (row0 + r < NN) ? Xv[idx] : make_float4(0.f, 0.f, 0.f, 0.f);
    }
    __syncthreads();

    int tx = tid & 31, ty = tid >> 5;
    int rb = ty * 8;

    unsigned long long acc[4][NCT];
    #pragma unroll
    for (int i = 0; i < 4; i++)
        #pragma unroll
        for (int j = 0; j < NCT; j++) acc[i][j] = 0ull;   // (0.f, 0.f)

    #pragma unroll 2
    for (int k = 0; k < DIN; k++) {
        unsigned long long ap[4];
        #pragma unroll
        for (int i = 0; i < 4; i++)
            ap[i] = pk2(xs[rb + 2*i][k], xs[rb + 2*i + 1][k]);

        const unsigned long long* bp =
            (const unsigned long long*)(Wd + (size_t)k * NC + tx * NCT);
        unsigned long long b[NCT];
        if (NCT == 4) {
            ulonglong2 b01 = ((const ulonglong2*)bp)[0];
            ulonglong2 b23 = ((const ulonglong2*)bp)[1];
            b[0] = b01.x; b[1] = b01.y; b[2] = b23.x; b[3] = b23.y;
        } else {
            ulonglong2 b01 = ((const ulonglong2*)bp)[0];
            b[0] = b01.x; b[1] = b01.y;
        }

        #pragma unroll
        for (int i = 0; i < 4; i++)
            #pragma unroll
            for (int j = 0; j < NCT; j++)
                fma2(acc[i][j], ap[i], b[j]);
    }

    // epilogue: scale by dinv[row], write NCT contiguous cols per row
    #pragma unroll
    for (int i = 0; i < 4; i++) {
        float2 vals[NCT];
        #pragma unroll
        for (int j = 0; j < NCT; j++) vals[j] = upk2(acc[i][j]);
        #pragma unroll
        for (int h = 0; h < 2; h++) {
            int row = row0 + rb + 2*i + h;
            if (row >= NN) continue;
            float dv = g_dinv[row];
            int col = tx * NCT;
            if (col >= ncOut) continue;
            float* dst = g_h + (size_t)row * ncOut + col;
            if (NCT == 4) {
                float4 o;
                o.x = (h ? vals[0].y : vals[0].x) * dv;
                o.y = (h ? vals[1].y : vals[1].x) * dv;
                o.z = (h ? vals[2].y : vals[2].x) * dv;
                o.w = (h ? vals[3].y : vals[3].x) * dv;
                *(float4*)dst = o;
            } else {
                float2 o;
                o.x = (h ? vals[0].y : vals[0].x) * dv;
                o.y = (h ? vals[1].y : vals[1].x) * dv;
                *(float2*)dst = o;
            }
        }
    }
}

// ---------------- aggregation: pull-mode CSR reduction (D=128) ----------------
// one warp per node; Xo[i] = relu( dinv[i]*(sum_{src} h'[src] + h'[i]) + b )
template<int DSTSEL>
__global__ void __launch_bounds__(256) aggregate_k(const float* __restrict__ bias) {
    int gw   = (blockIdx.x*blockDim.x + threadIdx.x) >> 5;
    int lane = threadIdx.x & 31;
    if (gw >= NN) return;
    const int NV = DH / 4;                  // 32 float4 per row -> all lanes

    const float4* Hv = (const float4*)(const float*)g_h;
    float* Xo = (DSTSEL == 1) ? (float*)g_x1 : (float*)g_x2;

    float4 acc = Hv[(size_t)gw * NV + lane];   // self-loop h'[i]

    int e   = g_rowptr[gw];
    int end = g_rowptr[gw + 1];
    for (; e + 7 < end; e += 8) {
        float4 v0 = Hv[(size_t)g_srcs[e  ] * NV + lane];
        float4 v1 = Hv[(size_t)g_srcs[e+1] * NV + lane];
        float4 v2 = Hv[(size_t)g_srcs[e+2] * NV + lane];
        float4 v3 = Hv[(size_t)g_srcs[e+3] * NV + lane];
        float4 v4 = Hv[(size_t)g_srcs[e+4] * NV + lane];
        float4 v5 = Hv[(size_t)g_srcs[e+5] * NV + lane];
        float4 v6 = Hv[(size_t)g_srcs[e+6] * NV + lane];
        float4 v7 = Hv[(size_t)g_srcs[e+7] * NV + lane];
        acc.x += ((v0.x+v1.x)+(v2.x+v3.x)) + ((v4.x+v5.x)+(v6.x+v7.x));
        acc.y += ((v0.y+v1.y)+(v2.y+v3.y)) + ((v4.y+v5.y)+(v6.y+v7.y));
        acc.z += ((v0.z+v1.z)+(v2.z+v3.z)) + ((v4.z+v5.z)+(v6.z+v7.z));
        acc.w += ((v0.w+v1.w)+(v2.w+v3.w)) + ((v4.w+v5.w)+(v6.w+v7.w));
    }
    for (; e < end; e++) {
        float4 v = Hv[(size_t)g_srcs[e] * NV + lane];
        acc.x += v.x; acc.y += v.y; acc.z += v.z; acc.w += v.w;
    }

    float dv  = g_dinv[gw];
    float4 bb = ((const float4*)bias)[lane];
    float4 o;
    o.x = fmaxf(fmaf(acc.x, dv, bb.x), 0.f);
    o.y = fmaxf(fmaf(acc.y, dv, bb.y), 0.f);
    o.z = fmaxf(fmaf(acc.z, dv, bb.z), 0.f);
    o.w = fmaxf(fmaf(acc.w, dv, bb.w), 0.f);
    ((float4*)Xo)[(size_t)gw * NV + lane] = o;
}

// ---------------- final layer: aggregate(40) + bias + relu + log_softmax ----------------
// one warp per node; lanes 0..9 hold the 40 cols as float4 each.
__global__ void __launch_bounds__(256) agg40_softmax_k(const float* __restrict__ bias,
                                                       float* __restrict__ out) {
    int gw   = (blockIdx.x*blockDim.x + threadIdx.x) >> 5;
    int lane = threadIdx.x & 31;
    if (gw >= NN) return;
    const int NV = DOUTC / 4;               // 10
    bool act = lane < NV;

    const float4* Hv = (const float4*)(const float*)g_h;

    // lanes >= NV read harmless in-bounds garbage (g_h is NN*DH floats)
    float4 acc = Hv[(size_t)gw * NV + lane];

    int e   = g_rowptr[gw];
    int end = g_rowptr[gw + 1];
    for (; e + 3 < end; e += 4) {
        float4 v0 = Hv[(size_t)g_srcs[e  ] * NV + lane];
        float4 v1 = Hv[(size_t)g_srcs[e+1] * NV + lane];
        float4 v2 = Hv[(size_t)g_srcs[e+2] * NV + lane];
        float4 v3 = Hv[(size_t)g_srcs[e+3] * NV + lane];
        acc.x += (v0.x+v1.x)+(v2.x+v3.x);
        acc.y += (v0.y+v1.y)+(v2.y+v3.y);
        acc.z += (v0.z+v1.z)+(v2.z+v3.z);
        acc.w += (v0.w+v1.w)+(v2.w+v3.w);
    }
    for (; e < end; e++) {
        float4 v = Hv[(size_t)g_srcs[e] * NV + lane];
        acc.x += v.x; acc.y += v.y; acc.z += v.z; acc.w += v.w;
    }

    float dv  = g_dinv[gw];
    float4 bb = act ? ((const float4*)bias)[lane] : make_float4(0.f,0.f,0.f,0.f);
    float4 o;
    o.x = fmaxf(fmaf(acc.x, dv, bb.x), 0.f);
    o.y = fmaxf(fmaf(acc.y, dv, bb.y), 0.f);
    o.z = fmaxf(fmaf(acc.z, dv, bb.z), 0.f);
    o.w = fmaxf(fmaf(acc.w, dv, bb.w), 0.f);

    // warp log_softmax over 40 values held in lanes 0..9
    float m = act ? fmaxf(fmaxf(o.x, o.y), fmaxf(o.z, o.w)) : -CUDART_INF_F;
    #pragma unroll
    for (int off = 16; off; off >>= 1)
        m = fmaxf(m, __shfl_xor_sync(0xffffffffu, m, off));
    float s = act ? (__expf(o.x - m) + __expf(o.y - m) +
                     __expf(o.z - m) + __expf(o.w - m)) : 0.f;
    #pragma unroll
    for (int off = 16; off; off >>= 1)
        s += __shfl_xor_sync(0xffffffffu, s, off);
    float lse = m + __logf(s);

    if (act) {
        float4 r;
        r.x = o.x - lse; r.y = o.y - lse; r.z = o.z - lse; r.w = o.w - lse;
        ((float4*)(out + (size_t)gw * DOUTC))[lane] = r;
    }
}

// ---------------- launch ----------------
extern "C" void kernel_launch(void* const* d_in, const int* in_sizes, int n_in,
                              void* d_out, int out_size) {
    const float* x  = (const float*)d_in[0];
    const int*   ei = (const int*)d_in[1];      // int32: JAX x64 disabled
    const float* W0 = (const float*)d_in[2];
    const float* b0 = (const float*)d_in[3];
    const float* W1 = (const float*)d_in[4];
    const float* b1 = (const float*)d_in[5];
    const float* W2 = (const float*)d_in[6];
    const float* b2 = (const float*)d_in[7];
    float* out = (float*)d_out;

    float2 *wd0, *wd1, *wd2;
    cudaGetSymbolAddress((void**)&wd0, g_wd0);
    cudaGetSymbolAddress((void**)&wd1, g_wd1);
    cudaGetSymbolAddress((void**)&wd2, g_wd2);

    // CSR build
    zero_deg_k  <<<(NN + 255)/256, 256>>>();
    count_deg_k <<<(EE + 255)/256, 256>>>(ei);
    scan1_k     <<<NB, 256>>>();
    scan2_k     <<<1, 256>>>();
    scan3_k     <<<NB, 256>>>();
    sort_edges_k<<<(EE + 255)/256, 256>>>(ei);

    // W duplication for f32x2 GEMM
    dupw_k<<<(DIN*DH + 255)/256, 256>>>(W0, wd0, DH, DH);
    dupw_k<<<(DIN*DH + 255)/256, 256>>>(W1, wd1, DH, DH);
    dupw_k<<<(DIN*64 + 255)/256, 256>>>(W2, wd2, DOUTC, 64);

    const int GG = (NN + 63) / 64;          // gemm blocks (64 rows each)
    const int GA = (NN * 32 + 255) / 256;   // one warp per node

    // layer 0: x -> g_h -> g_x1
    gemm2_k<128, 0><<<GG, 256>>>(x, wd0, DH);
    aggregate_k<1><<<GA, 256>>>(b0);
    // layer 1: g_x1 -> g_h -> g_x2
    gemm2_k<128, 1><<<GG, 256>>>(nullptr, wd1, DH);
    aggregate_k<2><<<GA, 256>>>(b1);
    // layer 2: g_x2 -> g_h(40) -> out (fused aggregate + bias + relu + log_softmax)
    gemm2_k<64, 2><<<GG, 256>>>(nullptr, wd2, DOUTC);
    agg40_softmax_k<<<GA, 256>>>(b2, out);
}

// round 5
// speedup vs baseline: 1.0982x; 1.0982x over previous
#include <cuda_runtime.h>
#include <cuda_fp16.h>
#include <math.h>
#include <math_constants.h>

#define NN    50000
#define EE    800000
#define DIN   128
#define DH    128
#define DOUTC 40
#define NB    ((NN + 255) / 256)   // 196 scan blocks

// ---------------- device scratch (no allocs allowed) ----------------
__device__ __half g_h16[NN*DH];   // h' = (x@W)*dinv[row], fp16
__device__ float  g_x1[NN*DH];    // layer output ping (fp32)
__device__ float  g_x2[NN*DH];    // layer output pong (fp32)
__device__ float  g_dinv[NN];
__device__ int    g_deg[NN];
__device__ int    g_rowptr[NN+1];
__device__ int    g_cursor[NN];
__device__ int    g_srcs[EE];     // edge srcs sorted by dst (CSR)
__device__ int    g_bsum[NB];
__device__ float2 g_wd0[DIN*DH];  // duplicated weight pairs
__device__ float2 g_wd1[DH*DH];
__device__ float2 g_wd2[DH*64];   // padded 40->64 cols

// ---------------- f32x2 helpers ----------------
__device__ __forceinline__ unsigned long long pk2(float lo, float hi) {
    unsigned long long r;
    asm("mov.b64 %0, {%1, %2};" : "=l"(r) : "f"(lo), "f"(hi));
    return r;
}
__device__ __forceinline__ void fma2(unsigned long long& d, unsigned long long a,
                                     unsigned long long b) {
    asm("fma.rn.f32x2 %0, %1, %2, %3;" : "=l"(d) : "l"(a), "l"(b), "l"(d));
}
__device__ __forceinline__ float2 upk2(unsigned long long v) {
    float2 f;
    asm("mov.b64 {%0, %1}, %2;" : "=f"(f.x), "=f"(f.y) : "l"(v));
    return f;
}

// ---------------- preprocessing ----------------
// edge_index is int32 (JAX x64 disabled): [0:EE)=src, [EE:2EE)=dst
__global__ void count_deg_k(const int* __restrict__ ei) {
    int e = blockIdx.x*blockDim.x + threadIdx.x;
    if (e < EE) {
        unsigned d = (unsigned)ei[EE + e];
        if (d < NN) atomicAdd(&g_deg[d], 1);
    }
}

// per-block degree sums + dinv
__global__ void scan1_k() {
    __shared__ int sd[256];
    int tid = threadIdx.x;
    int i = blockIdx.x*256 + tid;
    int d = (i < NN) ? g_deg[i] : 0;
    if (i < NN) g_dinv[i] = rsqrtf((float)(d + 1));   // +1 self-loop
    sd[tid] = d;
    __syncthreads();
    for (int off = 128; off; off >>= 1) {
        if (tid < off) sd[tid] += sd[tid + off];
        __syncthreads();
    }
    if (tid == 0) g_bsum[blockIdx.x] = sd[0];
}

// fused: per-block offset (redundant reduction of g_bsum) + intra-block scan
__global__ void scan23_k() {
    __shared__ int sd[256];
    int b = blockIdx.x, tid = threadIdx.x;

    int p = 0;
    for (int j = tid; j < b; j += 256) p += g_bsum[j];
    sd[tid] = p;
    __syncthreads();
    for (int off = 128; off; off >>= 1) {
        if (tid < off) sd[tid] += sd[tid + off];
        __syncthreads();
    }
    int base0 = sd[0];
    __syncthreads();

    int i = b*256 + tid;
    int d = (i < NN) ? g_deg[i] : 0;
    sd[tid] = d;
    __syncthreads();
    for (int off = 1; off < 256; off <<= 1) {
        int t = (tid >= off) ? sd[tid - off] : 0;
        __syncthreads();
        sd[tid] += t;
        __syncthreads();
    }
    if (i < NN) {
        int base = base0 + sd[tid] - d;   // exclusive
        g_rowptr[i] = base;
        g_cursor[i] = base;
    }
    if (b == NB-1 && tid == 255) g_rowptr[NN] = base0 + sd[255];
}

__global__ void sort_edges_k(const int* __restrict__ ei) {
    int e = blockIdx.x*blockDim.x + threadIdx.x;
    if (e < EE) {
        unsigned d = (unsigned)ei[EE + e];
        unsigned s = (unsigned)ei[e];
        if (d < NN && s < NN) {
            int pos = atomicAdd(&g_cursor[d], 1);
            if (pos < EE) g_srcs[pos] = (int)s;
        }
    }
}

// ---------------- W duplication (all three weights, one kernel) ----------------
__global__ void dupw_all_k(const float* __restrict__ W0,
                           const float* __restrict__ W1,
                           const float* __restrict__ W2) {
    const int T0 = DIN*DH, T1 = T0 + DH*DH, T2 = T1 + DH*64;
    int idx = blockIdx.x*blockDim.x + threadIdx.x;
    if (idx < T0) {
        float w = W0[idx];
        g_wd0[idx] = make_float2(w, w);
    } else if (idx < T1) {
        float w = W1[idx - T0];
        g_wd1[idx - T0] = make_float2(w, w);
    } else if (idx < T2) {
        int j = idx - T1;
        int k = j / 64, c = j % 64;
        float w = (c < DOUTC) ? W2[k*DOUTC + c] : 0.f;
        g_wd2[j] = make_float2(w, w);
    }
}

// ---------------- GEMM: H16 = (X @ W) * dinv[row], f32x2 packed ----------------
// 256 threads, 64 rows/block. Thread: 8 rows (4 pairs) x NCT cols. NCT = NC/32.
template<int NC, int SRCSEL>
__global__ void __launch_bounds__(256) gemm2_k(const float* __restrict__ Xp,
                                               const float2* __restrict__ Wd,
                                               int ncOut) {
    const int NCT = NC / 32;
    const float* X = (SRCSEL == 0) ? Xp : (SRCSEL == 1 ? (const float*)g_x1
                                                       : (const float*)g_x2);
    __shared__ float xs[64][DIN];            // 32 KB
    int tid  = threadIdx.x;
    int row0 = blockIdx.x * 64;

    const float4* Xv = (const float4*)(X + (size_t)row0 * DIN);
    float4* xsv = (float4*)&xs[0][0];
    #pragma unroll
    for (int i = 0; i < 8; i++) {
        int idx = tid + i * 256;
        int r = idx >> 5;
        xsv[idx] = (row0 + r < NN) ? Xv[idx] : make_float4(0.f, 0.f, 0.f, 0.f);
    }
    __syncthreads();

    int tx = tid & 31, ty = tid >> 5;
    int rb = ty * 8;

    unsigned long long acc[4][NCT];
    #pragma unroll
    for (int i = 0; i < 4; i++)
        #pragma unroll
        for (int j = 0; j < NCT; j++) acc[i][j] = 0ull;

    #pragma unroll 2
    for (int k = 0; k < DIN; k++) {
        unsigned long long ap[4];
        #pragma unroll
        for (int i = 0; i < 4; i++)
            ap[i] = pk2(xs[rb + 2*i][k], xs[rb + 2*i + 1][k]);

        const unsigned long long* bp =
            (const unsigned long long*)(Wd + (size_t)k * NC + tx * NCT);
        unsigned long long b[NCT];
        if (NCT == 4) {
            ulonglong2 b01 = ((const ulonglong2*)bp)[0];
            ulonglong2 b23 = ((const ulonglong2*)bp)[1];
            b[0] = b01.x; b[1] = b01.y; b[2] = b23.x; b[3] = b23.y;
        } else {
            ulonglong2 b01 = ((const ulonglong2*)bp)[0];
            b[0] = b01.x; b[1] = b01.y;
        }

        #pragma unroll
        for (int i = 0; i < 4; i++)
            #pragma unroll
            for (int j = 0; j < NCT; j++)
                fma2(acc[i][j], ap[i], b[j]);
    }

    // epilogue: scale by dinv[row], pack fp16, write
    #pragma unroll
    for (int i = 0; i < 4; i++) {
        float2 vals[NCT];
        #pragma unroll
        for (int j = 0; j < NCT; j++) vals[j] = upk2(acc[i][j]);
        #pragma unroll
        for (int h = 0; h < 2; h++) {
            int row = row0 + rb + 2*i + h;
            if (row >= NN) continue;
            int col = tx * NCT;
            if (col >= ncOut) continue;
            float dv = g_dinv[row];
            __half* dst = g_h16 + (size_t)row * ncOut + col;
            if (NCT == 4) {
                float s0 = (h ? vals[0].y : vals[0].x) * dv;
                float s1 = (h ? vals[1].y : vals[1].x) * dv;
                float s2 = (h ? vals[2].y : vals[2].x) * dv;
                float s3 = (h ? vals[3].y : vals[3].x) * dv;
                __half2 p0 = __floats2half2_rn(s0, s1);
                __half2 p1 = __floats2half2_rn(s2, s3);
                uint2 o;
                o.x = *(unsigned*)&p0;
                o.y = *(unsigned*)&p1;
                *(uint2*)dst = o;
            } else {
                float s0 = (h ? vals[0].y : vals[0].x) * dv;
                float s1 = (h ? vals[1].y : vals[1].x) * dv;
                __half2 p0 = __floats2half2_rn(s0, s1);
                *(unsigned*)dst = *(unsigned*)&p0;
            }
        }
    }
}

// ---------------- aggregation (D=128, fp16 gathers, fp32 accumulate) ----------------
__device__ __forceinline__ void acc_row(float4& acc, uint2 u) {
    float2 f0 = __half22float2(*(__half2*)&u.x);
    float2 f1 = __half22float2(*(__half2*)&u.y);
    acc.x += f0.x; acc.y += f0.y; acc.z += f1.x; acc.w += f1.y;
}

template<int DSTSEL>
__global__ void __launch_bounds__(256) aggregate_k(const float* __restrict__ bias) {
    int gw   = (blockIdx.x*blockDim.x + threadIdx.x) >> 5;
    int lane = threadIdx.x & 31;
    if (gw >= NN) return;

    const __half* H = g_h16;
    float* Xo = (DSTSEL == 1) ? (float*)g_x1 : (float*)g_x2;
    int co = lane * 4;   // 4 halves per lane -> 128 cols

    float4 acc = make_float4(0.f, 0.f, 0.f, 0.f);
    acc_row(acc, *(const uint2*)(H + (size_t)gw * DH + co));   // self-loop

    int e   = g_rowptr[gw];
    int end = g_rowptr[gw + 1];
    for (; e + 7 < end; e += 8) {
        uint2 u0 = *(const uint2*)(H + (size_t)g_srcs[e  ] * DH + co);
        uint2 u1 = *(const uint2*)(H + (size_t)g_srcs[e+1] * DH + co);
        uint2 u2 = *(const uint2*)(H + (size_t)g_srcs[e+2] * DH + co);
        uint2 u3 = *(const uint2*)(H + (size_t)g_srcs[e+3] * DH + co);
        uint2 u4 = *(const uint2*)(H + (size_t)g_srcs[e+4] * DH + co);
        uint2 u5 = *(const uint2*)(H + (size_t)g_srcs[e+5] * DH + co);
        uint2 u6 = *(const uint2*)(H + (size_t)g_srcs[e+6] * DH + co);
        uint2 u7 = *(const uint2*)(H + (size_t)g_srcs[e+7] * DH + co);
        acc_row(acc, u0); acc_row(acc, u1); acc_row(acc, u2); acc_row(acc, u3);
        acc_row(acc, u4); acc_row(acc, u5); acc_row(acc, u6); acc_row(acc, u7);
    }
    for (; e < end; e++)
        acc_row(acc, *(const uint2*)(H + (size_t)g_srcs[e] * DH + co));

    float dv  = g_dinv[gw];
    float4 bb = ((const float4*)bias)[lane];
    float4 o;
    o.x = fmaxf(fmaf(acc.x, dv, bb.x), 0.f);
    o.y = fmaxf(fmaf(acc.y, dv, bb.y), 0.f);
    o.z = fmaxf(fmaf(acc.z, dv, bb.z), 0.f);
    o.w = fmaxf(fmaf(acc.w, dv, bb.w), 0.f);
    ((float4*)Xo)[(size_t)gw * (DH/4) + lane] = o;
}

// ---------------- final layer: aggregate(40) + bias + relu + log_softmax ----------------
__global__ void __launch_bounds__(256) agg40_softmax_k(const float* __restrict__ bias,
                                                       float* __restrict__ out) {
    int gw   = (blockIdx.x*blockDim.x + threadIdx.x) >> 5;
    int lane = threadIdx.x & 31;
    if (gw >= NN) return;
    const int NV = DOUTC / 4;               // 10 active lanes
    bool act = lane < NV;

    const __half* H = g_h16;
    int co = lane * 4;

    float4 acc = make_float4(0.f, 0.f, 0.f, 0.f);
    float4 o   = make_float4(0.f, 0.f, 0.f, 0.f);

    if (act) {
        acc_row(acc, *(const uint2*)(H + (size_t)gw * DOUTC + co));   // self-loop
        int e   = g_rowptr[gw];
        int end = g_rowptr[gw + 1];
        for (; e + 3 < end; e += 4) {
            uint2 u0 = *(const uint2*)(H + (size_t)g_srcs[e  ] * DOUTC + co);
            uint2 u1 = *(const uint2*)(H + (size_t)g_srcs[e+1] * DOUTC + co);
            uint2 u2 = *(const uint2*)(H + (size_t)g_srcs[e+2] * DOUTC + co);
            uint2 u3 = *(const uint2*)(H + (size_t)g_srcs[e+3] * DOUTC + co);
            acc_row(acc, u0); acc_row(acc, u1); acc_row(acc, u2); acc_row(acc, u3);
        }
        for (; e < end; e++)
            acc_row(acc, *(const uint2*)(H + (size_t)g_srcs[e] * DOUTC + co));

        float dv  = g_dinv[gw];
        float4 bb = ((const float4*)bias)[lane];
        o.x = fmaxf(fmaf(acc.x, dv, bb.x), 0.f);
        o.y = fmaxf(fmaf(acc.y, dv, bb.y), 0.f);
        o.z = fmaxf(fmaf(acc.z, dv, bb.z), 0.f);
        o.w = fmaxf(fmaf(acc.w, dv, bb.w), 0.f);
    }

    float m = act ? fmaxf(fmaxf(o.x, o.y), fmaxf(o.z, o.w)) : -CUDART_INF_F;
    #pragma unroll
    for (int off = 16; off; off >>= 1)
        m = fmaxf(m, __shfl_xor_sync(0xffffffffu, m, off));
    float s = act ? (__expf(o.x - m) + __expf(o.y - m) +
                     __expf(o.z - m) + __expf(o.w - m)) : 0.f;
    #pragma unroll
    for (int off = 16; off; off >>= 1)
        s += __shfl_xor_sync(0xffffffffu, s, off);
    float lse = m + __logf(s);

    if (act) {
        float4 r;
        r.x = o.x - lse; r.y = o.y - lse; r.z = o.z - lse; r.w = o.w - lse;
        ((float4*)(out + (size_t)gw * DOUTC))[lane] = r;
    }
}

// ---------------- launch ----------------
extern "C" void kernel_launch(void* const* d_in, const int* in_sizes, int n_in,
                              void* d_out, int out_size) {
    const float* x  = (const float*)d_in[0];
    const int*   ei = (const int*)d_in[1];      // int32: JAX x64 disabled
    const float* W0 = (const float*)d_in[2];
    const float* b0 = (const float*)d_in[3];
    const float* W1 = (const float*)d_in[4];
    const float* b1 = (const float*)d_in[5];
    const float* W2 = (const float*)d_in[6];
    const float* b2 = (const float*)d_in[7];
    float* out = (float*)d_out;

    float2 *wd0, *wd1, *wd2;
    void* degp;
    cudaGetSymbolAddress((void**)&wd0, g_wd0);
    cudaGetSymbolAddress((void**)&wd1, g_wd1);
    cudaGetSymbolAddress((void**)&wd2, g_wd2);
    cudaGetSymbolAddress(&degp, g_deg);

    const int TDUP = DIN*DH + DH*DH + DH*64;
    const int GG = (NN + 63) / 64;
    const int GA = (NN * 32 + 255) / 256;

    cudaMemsetAsync(degp, 0, NN*sizeof(int));
    dupw_all_k  <<<(TDUP + 255)/256, 256>>>(W0, W1, W2);        // 1
    count_deg_k <<<(EE + 255)/256, 256>>>(ei);                  // 2
    scan1_k     <<<NB, 256>>>();                                // 3 (dinv ready)
    gemm2_k<128, 0><<<GG, 256>>>(x, wd0, DH);                   // 4 <- profiled slot
    scan23_k    <<<NB, 256>>>();                                // 5
    sort_edges_k<<<(EE + 255)/256, 256>>>(ei);                  // 6
    aggregate_k<1><<<GA, 256>>>(b0);                            // 7
    gemm2_k<128, 1><<<GG, 256>>>(nullptr, wd1, DH);             // 8
    aggregate_k<2><<<GA, 256>>>(b1);                            // 9
    gemm2_k<64, 2><<<GG, 256>>>(nullptr, wd2, DOUTC);           // 10
    agg40_softmax_k<<<GA, 256>>>(b2, out);                      // 11
}

// round 7
// speedup vs baseline: 1.8237x; 1.6607x over previous
#include <cuda_runtime.h>
#include <cuda_fp16.h>
#include <mma.h>
#include <math.h>
#include <math_constants.h>

using namespace nvcuda;

#define NN    50000
#define EE    800000
#define DIN   128
#define DH    128
#define DOUTC 40
#define NB    ((NN + 255) / 256)    // 196 scan blocks
#define NROWP 50048                 // 391 * 128, NN rounded up

// ---------------- device scratch (no allocs allowed) ----------------
__device__ __half g_a16[NROWP*DH];  // GEMM input (cvt(x) / aggregate output)
__device__ __half g_h16[NROWP*DH];  // GEMM output h = A @ W (fp16)
__device__ __half g_w0h[DIN*DH];
__device__ __half g_w1h[DH*DH];
__device__ __half g_w2h[DH*64];     // padded 40->64 cols
__device__ float  g_dinv[NN];
__device__ int    g_deg[NN];
__device__ int    g_rowptr[NN+1];
__device__ int    g_cursor[NN];
__device__ int    g_srcs[EE];       // edge srcs sorted by dst (CSR)
__device__ int    g_bsum[NB];

// ---------------- x -> fp16 ----------------
__global__ void cvt_x_k(const float* __restrict__ x) {
    int i = blockIdx.x*blockDim.x + threadIdx.x;     // float4 index
    if (i < NN*DH/4) {
        float4 v = ((const float4*)x)[i];
        __half2 h0 = __floats2half2_rn(v.x, v.y);
        __half2 h1 = __floats2half2_rn(v.z, v.w);
        uint2 o; o.x = *(unsigned*)&h0; o.y = *(unsigned*)&h1;
        ((uint2*)g_a16)[i] = o;
    }
}

// ---------------- W -> fp16 (all three, one kernel) ----------------
__global__ void dupw_all_k(const float* __restrict__ W0,
                           const float* __restrict__ W1,
                           const float* __restrict__ W2) {
    const int T0 = DIN*DH, T1 = T0 + DH*DH, T2 = T1 + DH*64;
    int idx = blockIdx.x*blockDim.x + threadIdx.x;
    if (idx < T0) {
        g_w0h[idx] = __float2half(W0[idx]);
    } else if (idx < T1) {
        g_w1h[idx - T0] = __float2half(W1[idx - T0]);
    } else if (idx < T2) {
        int j = idx - T1;
        int k = j / 64, c = j % 64;
        g_w2h[j] = __float2half((c < DOUTC) ? W2[k*DOUTC + c] : 0.f);
    }
}

// ---------------- preprocessing ----------------
// edge_index is int32 (JAX x64 disabled): [0:EE)=src, [EE:2EE)=dst
__global__ void count_deg_k(const int* __restrict__ ei) {
    int e = blockIdx.x*blockDim.x + threadIdx.x;
    if (e < EE) {
        unsigned d = (unsigned)ei[EE + e];
        if (d < NN) atomicAdd(&g_deg[d], 1);
    }
}

__global__ void scan1_k() {
    __shared__ int sd[256];
    int tid = threadIdx.x;
    int i = blockIdx.x*256 + tid;
    int d = (i < NN) ? g_deg[i] : 0;
    if (i < NN) g_dinv[i] = rsqrtf((float)(d + 1));   // +1 self-loop
    sd[tid] = d;
    __syncthreads();
    for (int off = 128; off; off >>= 1) {
        if (tid < off) sd[tid] += sd[tid + off];
        __syncthreads();
    }
    if (tid == 0) g_bsum[blockIdx.x] = sd[0];
}

__global__ void scan23_k() {
    __shared__ int sd[256];
    int b = blockIdx.x, tid = threadIdx.x;

    int p = 0;
    for (int j = tid; j < b; j += 256) p += g_bsum[j];
    sd[tid] = p;
    __syncthreads();
    for (int off = 128; off; off >>= 1) {
        if (tid < off) sd[tid] += sd[tid + off];
        __syncthreads();
    }
    int base0 = sd[0];
    __syncthreads();

    int i = b*256 + tid;
    int d = (i < NN) ? g_deg[i] : 0;
    sd[tid] = d;
    __syncthreads();
    for (int off = 1; off < 256; off <<= 1) {
        int t = (tid >= off) ? sd[tid - off] : 0;
        __syncthreads();
        sd[tid] += t;
        __syncthreads();
    }
    if (i < NN) {
        int base = base0 + sd[tid] - d;   // exclusive
        g_rowptr[i] = base;
        g_cursor[i] = base;
    }
    if (b == NB-1 && tid == 255) g_rowptr[NN] = base0 + sd[255];
}

__global__ void sort_edges_k(const int* __restrict__ ei) {
    int e = blockIdx.x*blockDim.x + threadIdx.x;
    if (e < EE) {
        unsigned d = (unsigned)ei[EE + e];
        unsigned s = (unsigned)ei[e];
        if (d < NN && s < NN) {
            int pos = atomicAdd(&g_cursor[d], 1);
            if (pos < EE) g_srcs[pos] = (int)s;
        }
    }
}

// ---------------- GEMM: g_h16 = g_a16 @ W  (wmma fp16, fp32 accum) ----------------
// 256 threads = 8 warps; block = 128 rows; warp = 16 rows x NC cols.
// NC: padded cols (128 or 64). NCOUT: true output stride (128 or 40).
template<int NC, int NCOUT>
__global__ void __launch_bounds__(256) gemm_wmma_k(const __half* __restrict__ B) {
    __shared__ __half  Ws[DIN][NC];          // 32KB (NC=128) / 16KB (NC=64)
    __shared__ float   scratch[8][16][16];   // 8KB epilogue staging

    int tid = threadIdx.x, wid = tid >> 5, lane = tid & 31;
    int row0 = blockIdx.x * 128 + wid * 16;

    // stage W (vector copy)
    const int NV4 = DIN * NC / 8;            // uint4 count
    #pragma unroll
    for (int i = tid; i < NV4; i += 256)
        ((uint4*)&Ws[0][0])[i] = ((const uint4*)B)[i];
    __syncthreads();

    if (row0 >= NN) return;                  // whole-warp OOB (last block)

    wmma::fragment<wmma::accumulator, 16, 16, 16, float> acc[NC/16];
    #pragma unroll
    for (int j = 0; j < NC/16; j++) wmma::fill_fragment(acc[j], 0.f);

    const __half* A = g_a16 + (size_t)row0 * DIN;
    #pragma unroll
    for (int k = 0; k < DIN; k += 16) {
        wmma::fragment<wmma::matrix_a, 16, 16, 16, __half, wmma::row_major> af;
        wmma::load_matrix_sync(af, A + k, DIN);
        #pragma unroll
        for (int j = 0; j < NC/16; j++) {
            wmma::fragment<wmma::matrix_b, 16, 16, 16, __half, wmma::row_major> bf;
            wmma::load_matrix_sync(bf, &Ws[k][j*16], NC);
            wmma::mma_sync(acc[j], af, bf, acc[j]);
        }
    }

    // epilogue: frag -> smem -> fp16 global (stride NCOUT, cols >= NCOUT dropped)
    int r = lane >> 1, c = (lane & 1) * 8;
    #pragma unroll
    for (int j = 0; j < NC/16; j++) {
        wmma::store_matrix_sync(&scratch[wid][0][0], acc[j], 16, wmma::mem_row_major);
        __syncwarp();
        int gcol = j*16 + c;
        if (gcol < NCOUT) {
            float* s = &scratch[wid][r][c];
            __half2 h0 = __floats2half2_rn(s[0], s[1]);
            __half2 h1 = __floats2half2_rn(s[2], s[3]);
            __half2 h2 = __floats2half2_rn(s[4], s[5]);
            __half2 h3 = __floats2half2_rn(s[6], s[7]);
            __half* dst = g_h16 + (size_t)(row0 + r) * NCOUT + gcol;
            uint2 o0; o0.x = *(unsigned*)&h0; o0.y = *(unsigned*)&h1;
            uint2 o1; o1.x = *(unsigned*)&h2; o1.y = *(unsigned*)&h3;
            ((uint2*)dst)[0] = o0;
            ((uint2*)dst)[1] = o1;
        }
        __syncwarp();
    }
}

// ---------------- aggregation (D=128): fp16 gathers, fp32 accumulate ----------------
// out[i] = relu( dinv[i]*( sum_e dinv[src]*h[src] + dinv[i]*h[i] ) + b ), fp16 out
__device__ __forceinline__ void accf(float4& acc, uint2 u, float dv) {
    float2 f0 = __half22float2(*(__half2*)&u.x);
    float2 f1 = __half22float2(*(__half2*)&u.y);
    acc.x = fmaf(f0.x, dv, acc.x);
    acc.y = fmaf(f0.y, dv, acc.y);
    acc.z = fmaf(f1.x, dv, acc.z);
    acc.w = fmaf(f1.y, dv, acc.w);
}

__global__ void __launch_bounds__(256) aggregate_k(const float* __restrict__ bias) {
    int gw   = (blockIdx.x*blockDim.x + threadIdx.x) >> 5;
    int lane = threadIdx.x & 31;
    if (gw >= NN) return;

    const __half* H = g_h16;
    int co = lane * 4;
    float dvi = g_dinv[gw];

    float4 acc = make_float4(0.f, 0.f, 0.f, 0.f);
    accf(acc, *(const uint2*)(H + (size_t)gw * DH + co), dvi);   // self-loop

    int e   = g_rowptr[gw];
    int end = g_rowptr[gw + 1];
    for (; e + 3 < end; e += 4) {
        int s0 = g_srcs[e], s1 = g_srcs[e+1], s2 = g_srcs[e+2], s3 = g_srcs[e+3];
        float d0 = g_dinv[s0], d1 = g_dinv[s1], d2 = g_dinv[s2], d3 = g_dinv[s3];
        uint2 u0 = *(const uint2*)(H + (size_t)s0 * DH + co);
        uint2 u1 = *(const uint2*)(H + (size_t)s1 * DH + co);
        uint2 u2 = *(const uint2*)(H + (size_t)s2 * DH + co);
        uint2 u3 = *(const uint2*)(H + (size_t)s3 * DH + co);
        accf(acc, u0, d0); accf(acc, u1, d1);
        accf(acc, u2, d2); accf(acc, u3, d3);
    }
    for (; e < end; e++) {
        int s = g_srcs[e];
        accf(acc, *(const uint2*)(H + (size_t)s * DH + co), g_dinv[s]);
    }

    float4 bb = ((const float4*)bias)[lane];
    float ox = fmaxf(fmaf(acc.x, dvi, bb.x), 0.f);
    float oy = fmaxf(fmaf(acc.y, dvi, bb.y), 0.f);
    float oz = fmaxf(fmaf(acc.z, dvi, bb.z), 0.f);
    float ow = fmaxf(fmaf(acc.w, dvi, bb.w), 0.f);
    __half2 h0 = __floats2half2_rn(ox, oy);
    __half2 h1 = __floats2half2_rn(oz, ow);
    uint2 o; o.x = *(unsigned*)&h0; o.y = *(unsigned*)&h1;
    *(uint2*)(g_a16 + (size_t)gw * DH + co) = o;
}

// ---------------- final: aggregate(40) + bias + relu + log_softmax ----------------
__global__ void __launch_bounds__(256) agg40_softmax_k(const float* __restrict__ bias,
                                                       float* __restrict__ out) {
    int gw   = (blockIdx.x*blockDim.x + threadIdx.x) >> 5;
    int lane = threadIdx.x & 31;
    if (gw >= NN) return;
    const int NV = DOUTC / 4;               // 10 active lanes
    bool act = lane < NV;

    const __half* H = g_h16;
    int co = lane * 4;
    float dvi = g_dinv[gw];

    float4 o = make_float4(0.f, 0.f, 0.f, 0.f);
    if (act) {
        float4 acc = make_float4(0.f, 0.f, 0.f, 0.f);
        accf(acc, *(const uint2*)(H + (size_t)gw * DOUTC + co), dvi);
        int e   = g_rowptr[gw];
        int end = g_rowptr[gw + 1];
        for (; e + 3 < end; e += 4) {
            int s0 = g_srcs[e], s1 = g_srcs[e+1], s2 = g_srcs[e+2], s3 = g_srcs[e+3];
            float d0 = g_dinv[s0], d1 = g_dinv[s1], d2 = g_dinv[s2], d3 = g_dinv[s3];
            uint2 u0 = *(const uint2*)(H + (size_t)s0 * DOUTC + co);
            uint2 u1 = *(const uint2*)(H + (size_t)s1 * DOUTC + co);
            uint2 u2 = *(const uint2*)(H + (size_t)s2 * DOUTC + co);
            uint2 u3 = *(const uint2*)(H + (size_t)s3 * DOUTC + co);
            accf(acc, u0, d0); accf(acc, u1, d1);
            accf(acc, u2, d2); accf(acc, u3, d3);
        }
        for (; e < end; e++) {
            int s = g_srcs[e];
            accf(acc, *(const uint2*)(H + (size_t)s * DOUTC + co), g_dinv[s]);
        }
        float4 bb = ((const float4*)bias)[lane];
        o.x = fmaxf(fmaf(acc.x, dvi, bb.x), 0.f);
        o.y = fmaxf(fmaf(acc.y, dvi, bb.y), 0.f);
        o.z = fmaxf(fmaf(acc.z, dvi, bb.z), 0.f);
        o.w = fmaxf(fmaf(acc.w, dvi, bb.w), 0.f);
    }

    float m = act ? fmaxf(fmaxf(o.x, o.y), fmaxf(o.z, o.w)) : -CUDART_INF_F;
    #pragma unroll
    for (int off = 16; off; off >>= 1)
        m = fmaxf(m, __shfl_xor_sync(0xffffffffu, m, off));
    float s = act ? (__expf(o.x - m) + __expf(o.y - m) +
                     __expf(o.z - m) + __expf(o.w - m)) : 0.f;
    #pragma unroll
    for (int off = 16; off; off >>= 1)
        s += __shfl_xor_sync(0xffffffffu, s, off);
    float lse = m + __logf(s);

    if (act) {
        float4 r;
        r.x = o.x - lse; r.y = o.y - lse; r.z = o.z - lse; r.w = o.w - lse;
        ((float4*)(out + (size_t)gw * DOUTC))[lane] = r;
    }
}

// ---------------- launch ----------------
extern "C" void kernel_launch(void* const* d_in, const int* in_sizes, int n_in,
                              void* d_out, int out_size) {
    const float* x  = (const float*)d_in[0];
    const int*   ei = (const int*)d_in[1];      // int32: JAX x64 disabled
    const float* W0 = (const float*)d_in[2];
    const float* b0 = (const float*)d_in[3];
    const float* W1 = (const float*)d_in[4];
    const float* b1 = (const float*)d_in[5];
    const float* W2 = (const float*)d_in[6];
    const float* b2 = (const float*)d_in[7];
    float* out = (float*)d_out;

    __half *w0h, *w1h, *w2h;
    void* degp;
    cudaGetSymbolAddress((void**)&w0h, g_w0h);
    cudaGetSymbolAddress((void**)&w1h, g_w1h);
    cudaGetSymbolAddress((void**)&w2h, g_w2h);
    cudaGetSymbolAddress(&degp, g_deg);

    const int TDUP = DIN*DH + DH*DH + DH*64;
    const int GB = NROWP / 128;             // 391 gemm blocks
    const int GA = (NN * 32 + 255) / 256;   // one warp per node

    cudaMemsetAsync(degp, 0, NN*sizeof(int));
    cvt_x_k     <<<(NN*DH/4 + 255)/256, 256>>>(x);              // 1
    dupw_all_k  <<<(TDUP + 255)/256, 256>>>(W0, W1, W2);        // 2
    count_deg_k <<<(EE + 255)/256, 256>>>(ei);                  // 3
    gemm_wmma_k<128, 128><<<GB, 256>>>(w0h);                    // 4 <- profiled slot
    scan1_k     <<<NB, 256>>>();                                // 5
    scan23_k    <<<NB, 256>>>();                                // 6
    sort_edges_k<<<(EE + 255)/256, 256>>>(ei);                  // 7
    aggregate_k <<<GA, 256>>>(b0);                              // 8
    gemm_wmma_k<128, 128><<<GB, 256>>>(w1h);                    // 9
    aggregate_k <<<GA, 256>>>(b1);                              // 10
    gemm_wmma_k<64, 40><<<GB, 256>>>(w2h);                      // 11
    agg40_softmax_k<<<GA, 256>>>(b2, out);                      // 12
}

// round 9
// speedup vs baseline: 2.5804x; 1.4149x over previous
#include <cuda_runtime.h>
#include <cuda_fp16.h>
#include <mma.h>
#include <math.h>
#include <math_constants.h>

using namespace nvcuda;

#define NN    50000
#define EE    800000
#define DIN   128
#define DH    128
#define DOUTC 40
#define NB    ((NN + 255) / 256)    // 196 scan blocks
#define NROWP 50048                 // 391 * 128, NN rounded up

// ---------------- device scratch (no allocs allowed) ----------------
__device__ __half g_a16[NROWP*DH];  // GEMM input (cvt(x) / aggregate output)
__device__ __half g_h16[NROWP*DH];  // GEMM output h = A @ W (fp16)
__device__ __half g_w0h[DIN*DH];
__device__ __half g_w1h[DH*DH];
__device__ __half g_w2h[DH*64];     // padded 40->64 cols
__device__ float  g_dinv[NN];
__device__ int    g_deg[NN];
__device__ int    g_rowptr[NN+1];
__device__ int    g_cursor[NN];
__device__ int    g_srcs[EE];       // edge srcs sorted by dst (CSR)
__device__ int    g_bsum[NB];

// ---------------- x -> fp16 ----------------
__global__ void cvt_x_k(const float* __restrict__ x) {
    int i = blockIdx.x*blockDim.x + threadIdx.x;     // float4 index
    if (i < NN*DH/4) {
        float4 v = ((const float4*)x)[i];
        __half2 h0 = __floats2half2_rn(v.x, v.y);
        __half2 h1 = __floats2half2_rn(v.z, v.w);
        uint2 o; o.x = *(unsigned*)&h0; o.y = *(unsigned*)&h1;
        ((uint2*)g_a16)[i] = o;
    }
}

// ---------------- W -> fp16 (all three, one kernel) ----------------
__global__ void dupw_all_k(const float* __restrict__ W0,
                           const float* __restrict__ W1,
                           const float* __restrict__ W2) {
    const int T0 = DIN*DH, T1 = T0 + DH*DH, T2 = T1 + DH*64;
    int idx = blockIdx.x*blockDim.x + threadIdx.x;
    if (idx < T0) {
        g_w0h[idx] = __float2half(W0[idx]);
    } else if (idx < T1) {
        g_w1h[idx - T0] = __float2half(W1[idx - T0]);
    } else if (idx < T2) {
        int j = idx - T1;
        int k = j / 64, c = j % 64;
        g_w2h[j] = __float2half((c < DOUTC) ? W2[k*DOUTC + c] : 0.f);
    }
}

// ---------------- preprocessing ----------------
// edge_index is int32 (JAX x64 disabled): [0:EE)=src, [EE:2EE)=dst
__global__ void count_deg_k(const int* __restrict__ ei) {
    int e = blockIdx.x*blockDim.x + threadIdx.x;
    if (e < EE) {
        unsigned d = (unsigned)ei[EE + e];
        if (d < NN) atomicAdd(&g_deg[d], 1);
    }
}

__global__ void scan1_k() {
    __shared__ int sd[256];
    int tid = threadIdx.x;
    int i = blockIdx.x*256 + tid;
    int d = (i < NN) ? g_deg[i] : 0;
    if (i < NN) g_dinv[i] = rsqrtf((float)(d + 1));   // +1 self-loop
    sd[tid] = d;
    __syncthreads();
    for (int off = 128; off; off >>= 1) {
        if (tid < off) sd[tid] += sd[tid + off];
        __syncthreads();
    }
    if (tid == 0) g_bsum[blockIdx.x] = sd[0];
}

__global__ void scan23_k() {
    __shared__ int sd[256];
    int b = blockIdx.x, tid = threadIdx.x;

    int p = 0;
    for (int j = tid; j < b; j += 256) p += g_bsum[j];
    sd[tid] = p;
    __syncthreads();
    for (int off = 128; off; off >>= 1) {
        if (tid < off) sd[tid] += sd[tid + off];
        __syncthreads();
    }
    int base0 = sd[0];
    __syncthreads();

    int i = b*256 + tid;
    int d = (i < NN) ? g_deg[i] : 0;
    sd[tid] = d;
    __syncthreads();
    for (int off = 1; off < 256; off <<= 1) {
        int t = (tid >= off) ? sd[tid - off] : 0;
        __syncthreads();
        sd[tid] += t;
        __syncthreads();
    }
    if (i < NN) {
        int base = base0 + sd[tid] - d;   // exclusive
        g_rowptr[i] = base;
        g_cursor[i] = base;
    }
    if (b == NB-1 && tid == 255) g_rowptr[NN] = base0 + sd[255];
}

__global__ void sort_edges_k(const int* __restrict__ ei) {
    int e = blockIdx.x*blockDim.x + threadIdx.x;
    if (e < EE) {
        unsigned d = (unsigned)ei[EE + e];
        unsigned s = (unsigned)ei[e];
        if (d < NN && s < NN) {
            int pos = atomicAdd(&g_cursor[d], 1);
            if (pos < EE) g_srcs[pos] = (int)s;
        }
    }
}

// ---------------- GEMM: g_h16 = g_a16 @ W  (wmma fp16, fp32 accum) ----------------
// 256 threads = 8 warps; block = 128 rows; warp = 16 rows x NC cols.
// Ws padded to NC+8 halves/row -> conflict-free LDSM (row stride 272B:
// 8 consecutive rows' 16B chunks cover all 32 banks exactly once).
template<int NC, int NCOUT>
__global__ void __launch_bounds__(256) gemm_wmma_k(const __half* __restrict__ B) {
    const int SB = NC + 8;
    __shared__ __half  Ws[DIN][SB];          // 34KB (NC=128) / 18KB (NC=64)
    __shared__ float   scratch[8][16][20];   // padded rows (80B stride)

    int tid = threadIdx.x, wid = tid >> 5, lane = tid & 31;
    int row0 = blockIdx.x * 128 + wid * 16;

    // stage W with padding (uint4 = 8 halves; SB % 8 == 0 -> aligned rows)
    const int RV4 = NC / 8;                  // uint4 per source row
    #pragma unroll
    for (int i = tid; i < DIN * RV4; i += 256) {
        int r = i / RV4, c = i % RV4;
        ((uint4*)&Ws[r][0])[c] = ((const uint4*)B)[i];
    }
    __syncthreads();

    if (row0 >= NN) return;                  // whole-warp OOB (last block)

    wmma::fragment<wmma::accumulator, 16, 16, 16, float> acc[NC/16];
    #pragma unroll
    for (int j = 0; j < NC/16; j++) wmma::fill_fragment(acc[j], 0.f);

    const __half* A = g_a16 + (size_t)row0 * DIN;
    #pragma unroll
    for (int k = 0; k < DIN; k += 16) {
        wmma::fragment<wmma::matrix_a, 16, 16, 16, __half, wmma::row_major> af;
        wmma::load_matrix_sync(af, A + k, DIN);
        #pragma unroll
        for (int j = 0; j < NC/16; j++) {
            wmma::fragment<wmma::matrix_b, 16, 16, 16, __half, wmma::row_major> bf;
            wmma::load_matrix_sync(bf, &Ws[k][j*16], SB);
            wmma::mma_sync(acc[j], af, bf, acc[j]);
        }
    }

    // epilogue: frag -> smem -> fp16 global (stride NCOUT, cols >= NCOUT dropped)
    int r = lane >> 1, c = (lane & 1) * 8;
    #pragma unroll
    for (int j = 0; j < NC/16; j++) {
        wmma::store_matrix_sync(&scratch[wid][0][0], acc[j], 20, wmma::mem_row_major);
        __syncwarp();
        int gcol = j*16 + c;
        if (gcol < NCOUT) {
            float* s = &scratch[wid][r][c];
            __half2 h0 = __floats2half2_rn(s[0], s[1]);
            __half2 h1 = __floats2half2_rn(s[2], s[3]);
            __half2 h2 = __floats2half2_rn(s[4], s[5]);
            __half2 h3 = __floats2half2_rn(s[6], s[7]);
            __half* dst = g_h16 + (size_t)(row0 + r) * NCOUT + gcol;
            uint2 o0; o0.x = *(unsigned*)&h0; o0.y = *(unsigned*)&h1;
            uint2 o1; o1.x = *(unsigned*)&h2; o1.y = *(unsigned*)&h3;
            ((uint2*)dst)[0] = o0;
            ((uint2*)dst)[1] = o1;
        }
        __syncwarp();
    }
}

// ---------------- aggregation (D=128): fp16 gathers, fp32 accumulate ----------------
__device__ __forceinline__ void accf(float4& acc, uint2 u, float dv) {
    float2 f0 = __half22float2(*(__half2*)&u.x);
    float2 f1 = __half22float2(*(__half2*)&u.y);
    acc.x = fmaf(f0.x, dv, acc.x);
    acc.y = fmaf(f0.y, dv, acc.y);
    acc.z = fmaf(f1.x, dv, acc.z);
    acc.w = fmaf(f1.y, dv, acc.w);
}

__global__ void __launch_bounds__(256) aggregate_k(const float* __restrict__ bias) {
    int gw   = (blockIdx.x*blockDim.x + threadIdx.x) >> 5;
    int lane = threadIdx.x & 31;
    if (gw >= NN) return;

    const __half* H = g_h16;
    int co = lane * 4;
    float dvi = g_dinv[gw];

    float4 acc = make_float4(0.f, 0.f, 0.f, 0.f);
    accf(acc, *(const uint2*)(H + (size_t)gw * DH + co), dvi);   // self-loop

    int e   = g_rowptr[gw];
    int end = g_rowptr[gw + 1];
    for (; e + 3 < end; e += 4) {
        int s0 = g_srcs[e], s1 = g_srcs[e+1], s2 = g_srcs[e+2], s3 = g_srcs[e+3];
        float d0 = g_dinv[s0], d1 = g_dinv[s1], d2 = g_dinv[s2], d3 = g_dinv[s3];
        uint2 u0 = *(const uint2*)(H + (size_t)s0 * DH + co);
        uint2 u1 = *(const uint2*)(H + (size_t)s1 * DH + co);
        uint2 u2 = *(const uint2*)(H + (size_t)s2 * DH + co);
        uint2 u3 = *(const uint2*)(H + (size_t)s3 * DH + co);
        accf(acc, u0, d0); accf(acc, u1, d1);
        accf(acc, u2, d2); accf(acc, u3, d3);
    }
    for (; e < end; e++) {
        int s = g_srcs[e];
        accf(acc, *(const uint2*)(H + (size_t)s * DH + co), g_dinv[s]);
    }

    float4 bb = ((const float4*)bias)[lane];
    float ox = fmaxf(fmaf(acc.x, dvi, bb.x), 0.f);
    float oy = fmaxf(fmaf(acc.y, dvi, bb.y), 0.f);
    float oz = fmaxf(fmaf(acc.z, dvi, bb.z), 0.f);
    float ow = fmaxf(fmaf(acc.w, dvi, bb.w), 0.f);
    __half2 h0 = __floats2half2_rn(ox, oy);
    __half2 h1 = __floats2half2_rn(oz, ow);
    uint2 o; o.x = *(unsigned*)&h0; o.y = *(unsigned*)&h1;
    *(uint2*)(g_a16 + (size_t)gw * DH + co) = o;
}

// ---------------- final: aggregate(40) + bias + relu + log_softmax ----------------
__global__ void __launch_bounds__(256) agg40_softmax_k(const float* __restrict__ bias,
                                                       float* __restrict__ out) {
    int gw   = (blockIdx.x*blockDim.x + threadIdx.x) >> 5;
    int lane = threadIdx.x & 31;
    if (gw >= NN) return;
    const int NV = DOUTC / 4;               // 10 active lanes
    bool act = lane < NV;

    const __half* H = g_h16;
    int co = lane * 4;
    float dvi = g_dinv[gw];

    float4 o = make_float4(0.f, 0.f, 0.f, 0.f);
    if (act) {
        float4 acc = make_float4(0.f, 0.f, 0.f, 0.f);
        accf(acc, *(const uint2*)(H + (size_t)gw * DOUTC + co), dvi);
        int e   = g_rowptr[gw];
        int end = g_rowptr[gw + 1];
        for (; e + 3 < end; e += 4) {
            int s0 = g_srcs[e], s1 = g_srcs[e+1], s2 = g_srcs[e+2], s3 = g_srcs[e+3];
            float d0 = g_dinv[s0], d1 = g_dinv[s1], d2 = g_dinv[s2], d3 = g_dinv[s3];
            uint2 u0 = *(const uint2*)(H + (size_t)s0 * DOUTC + co);
            uint2 u1 = *(const uint2*)(H + (size_t)s1 * DOUTC + co);
            uint2 u2 = *(const uint2*)(H + (size_t)s2 * DOUTC + co);
            uint2 u3 = *(const uint2*)(H + (size_t)s3 * DOUTC + co);
            accf(acc, u0, d0); accf(acc, u1, d1);
            accf(acc, u2, d2); accf(acc, u3, d3);
        }
        for (; e < end; e++) {
            int s = g_srcs[e];
            accf(acc, *(const uint2*)(H + (size_t)s * DOUTC + co), g_dinv[s]);
        }
        float4 bb = ((const float4*)bias)[lane];
        o.x = fmaxf(fmaf(acc.x, dvi, bb.x), 0.f);
        o.y = fmaxf(fmaf(acc.y, dvi, bb.y), 0.f);
        o.z = fmaxf(fmaf(acc.z, dvi, bb.z), 0.f);
        o.w = fmaxf(fmaf(acc.w, dvi, bb.w), 0.f);
    }

    float m = act ? fmaxf(fmaxf(o.x, o.y), fmaxf(o.z, o.w)) : -CUDART_INF_F;
    #pragma unroll
    for (int off = 16; off; off >>= 1)
        m = fmaxf(m, __shfl_xor_sync(0xffffffffu, m, off));
    float s = act ? (__expf(o.x - m) + __expf(o.y - m) +
                     __expf(o.z - m) + __expf(o.w - m)) : 0.f;
    #pragma unroll
    for (int off = 16; off; off >>= 1)
        s += __shfl_xor_sync(0xffffffffu, s, off);
    float lse = m + __logf(s);

    if (act) {
        float4 r;
        r.x = o.x - lse; r.y = o.y - lse; r.z = o.z - lse; r.w = o.w - lse;
        ((float4*)(out + (size_t)gw * DOUTC))[lane] = r;
    }
}

// ---------------- launch ----------------
extern "C" void kernel_launch(void* const* d_in, const int* in_sizes, int n_in,
                              void* d_out, int out_size) {
    const float* x  = (const float*)d_in[0];
    const int*   ei = (const int*)d_in[1];      // int32: JAX x64 disabled
    const float* W0 = (const float*)d_in[2];
    const float* b0 = (const float*)d_in[3];
    const float* W1 = (const float*)d_in[4];
    const float* b1 = (const float*)d_in[5];
    const float* W2 = (const float*)d_in[6];
    const float* b2 = (const float*)d_in[7];
    float* out = (float*)d_out;

    __half *w0h, *w1h, *w2h;
    void* degp;
    cudaGetSymbolAddress((void**)&w0h, g_w0h);
    cudaGetSymbolAddress((void**)&w1h, g_w1h);
    cudaGetSymbolAddress((void**)&w2h, g_w2h);
    cudaGetSymbolAddress(&degp, g_deg);

    const int TDUP = DIN*DH + DH*DH + DH*64;
    const int GB = NROWP / 128;             // 391 gemm blocks
    const int GA = (NN * 32 + 255) / 256;   // one warp per node

    cudaMemsetAsync(degp, 0, NN*sizeof(int));
    cvt_x_k     <<<(NN*DH/4 + 255)/256, 256>>>(x);              // 1
    dupw_all_k  <<<(TDUP + 255)/256, 256>>>(W0, W1, W2);        // 2
    count_deg_k <<<(EE + 255)/256, 256>>>(ei);                  // 3
    gemm_wmma_k<128, 128><<<GB, 256>>>(w0h);                    // 4 <- profiled slot
    scan1_k     <<<NB, 256>>>();                                // 5
    scan23_k    <<<NB, 256>>>();                                // 6
    sort_edges_k<<<(EE + 255)/256, 256>>>(ei);                  // 7
    aggregate_k <<<GA, 256>>>(b0);                              // 8
    gemm_wmma_k<128, 128><<<GB, 256>>>(w1h);                    // 9
    aggregate_k <<<GA, 256>>>(b1);                              // 10
    gemm_wmma_k<64, 40><<<GB, 256>>>(w2h);                      // 11
    agg40_softmax_k<<<GA, 256>>>(b2, out);                      // 12
}

// round 15
// speedup vs baseline: 2.6337x; 1.0207x over previous
#include <cuda_runtime.h>
#include <cuda_fp16.h>
#include <mma.h>
#include <math.h>
#include <math_constants.h>

using namespace nvcuda;

#define NN    50000
#define EE    800000
#define DIN   128
#define DH    128
#define DOUTC 40
#define NB    ((NN + 255) / 256)    // 196 scan blocks
#define NROWP 50048                 // 391 * 128, NN rounded up

// ---------------- device scratch (no allocs allowed) ----------------
__device__ __half g_a16[NROWP*DH];  // GEMM input (cvt(x) / aggregate output)
__device__ __half g_h16[NROWP*DH];  // GEMM output h = A @ W (fp16)
__device__ __half g_w0h[DIN*DH];
__device__ __half g_w1h[DH*DH];
__device__ __half g_w2h[DH*64];     // padded 40->64 cols
__device__ float  g_dinv[NN];
__device__ int    g_deg[NN];
__device__ int    g_rowptr[NN+1];
__device__ int    g_cursor[NN];
__device__ int    g_srcs[EE];       // edge srcs sorted by dst (CSR)
__device__ int    g_bsum[NB];

// ---------------- fused pre: cvt(x) + W->fp16 + degree histogram ----------------
#define CVT_N   (NN*DH/4)                       // 1,600,000 float4
#define TDUP    (DIN*DH + DH*DH + DH*64)        // 40,960
#define PRE_TOT (CVT_N + EE + TDUP)

__global__ void fused_pre_k(const float* __restrict__ x,
                            const int*   __restrict__ ei,
                            const float* __restrict__ W0,
                            const float* __restrict__ W1,
                            const float* __restrict__ W2) {
    int idx = blockIdx.x*blockDim.x + threadIdx.x;
    if (idx < CVT_N) {
        float4 v = ((const float4*)x)[idx];
        __half2 h0 = __floats2half2_rn(v.x, v.y);
        __half2 h1 = __floats2half2_rn(v.z, v.w);
        uint2 o; o.x = *(unsigned*)&h0; o.y = *(unsigned*)&h1;
        ((uint2*)g_a16)[idx] = o;
    } else if (idx < CVT_N + EE) {
        int e = idx - CVT_N;
        unsigned d = (unsigned)ei[EE + e];
        if (d < NN) atomicAdd(&g_deg[d], 1);
    } else if (idx < PRE_TOT) {
        int j = idx - CVT_N - EE;
        const int T0 = DIN*DH, T1 = T0 + DH*DH;
        if (j < T0) {
            g_w0h[j] = __float2half(W0[j]);
        } else if (j < T1) {
            g_w1h[j - T0] = __float2half(W1[j - T0]);
        } else {
            int jj = j - T1;
            int k = jj / 64, c = jj % 64;
            g_w2h[jj] = __float2half((c < DOUTC) ? W2[k*DOUTC + c] : 0.f);
        }
    }
}

// ---------------- scans ----------------
__global__ void scan1_k() {
    __shared__ int sd[256];
    int tid = threadIdx.x;
    int i = blockIdx.x*256 + tid;
    int d = (i < NN) ? g_deg[i] : 0;
    if (i < NN) g_dinv[i] = rsqrtf((float)(d + 1));   // +1 self-loop
    sd[tid] = d;
    __syncthreads();
    for (int off = 128; off; off >>= 1) {
        if (tid < off) sd[tid] += sd[tid + off];
        __syncthreads();
    }
    if (tid == 0) g_bsum[blockIdx.x] = sd[0];
}

__global__ void scan23_k() {
    __shared__ int sd[256];
    int b = blockIdx.x, tid = threadIdx.x;

    int p = 0;
    for (int j = tid; j < b; j += 256) p += g_bsum[j];
    sd[tid] = p;
    __syncthreads();
    for (int off = 128; off; off >>= 1) {
        if (tid < off) sd[tid] += sd[tid + off];
        __syncthreads();
    }
    int base0 = sd[0];
    __syncthreads();

    int i = b*256 + tid;
    int d = (i < NN) ? g_deg[i] : 0;
    sd[tid] = d;
    __syncthreads();
    for (int off = 1; off < 256; off <<= 1) {
        int t = (tid >= off) ? sd[tid - off] : 0;
        __syncthreads();
        sd[tid] += t;
        __syncthreads();
    }
    if (i < NN) {
        int base = base0 + sd[tid] - d;   // exclusive
        g_rowptr[i] = base;
        g_cursor[i] = base;
    }
    if (b == NB-1 && tid == 255) g_rowptr[NN] = base0 + sd[255];
}

__global__ void sort_edges_k(const int* __restrict__ ei) {
    int e = blockIdx.x*blockDim.x + threadIdx.x;
    if (e < EE) {
        unsigned d = (unsigned)ei[EE + e];
        unsigned s = (unsigned)ei[e];
        if (d < NN && s < NN) {
            int pos = atomicAdd(&g_cursor[d], 1);
            if (pos < EE) g_srcs[pos] = (int)s;
        }
    }
}

// ---------------- GEMM v3: g_h16 = g_a16 @ W  (wmma fp16, fp32 accum) ----------------
// 256 threads = 8 warps; block tile = 128 rows x NC cols.
// Warp tile = 32 rows x NC/2 cols: wr = wid>>1 (row strip), wc = wid&1 (col strip).
// A staged in padded smem (stride 136 halves = 272B -> conflict-free LDSM),
// W staged likewise. Epilogue scratch overlays the A tile after a sync.
template<int NC, int NCOUT>
__global__ void __launch_bounds__(256) gemm3_k(const __half* __restrict__ B) {
    const int SA = DIN + 8;                  // 136
    const int SB = NC + 8;                   // 136 / 72
    const int NJ = NC / 32;                  // col frags per warp: 4 / 2
    extern __shared__ char smraw[];
    __half (*As)[SA] = (__half(*)[SA])smraw;                       // 128*272B = 34816
    __half (*Ws)[SB] = (__half(*)[SB])(smraw + 128*SA*2);
    float  (*scr)[16][20] = (float(*)[16][20])smraw;               // reused post-sync

    int tid = threadIdx.x, wid = tid >> 5, lane = tid & 31;
    int wr = wid >> 1, wc = wid & 1;
    int row0 = blockIdx.x * 128;

    // stage W (uint4 = 8 halves)
    const int WV = DIN * NC / 8;
    #pragma unroll
    for (int i = tid; i < WV; i += 256) {
        int r = i / (NC/8), c = i % (NC/8);
        ((uint4*)&Ws[r][0])[c] = ((const uint4*)B)[i];
    }
    // stage A: 128 rows x 16 uint4 (rows >= NN read zero padding of g_a16)
    #pragma unroll
    for (int i = tid; i < 128*16; i += 256) {
        int r = i >> 4, c = i & 15;
        ((uint4*)&As[r][0])[c] =
            ((const uint4*)(g_a16 + (size_t)(row0 + r) * DIN))[c];
    }
    __syncthreads();

    wmma::fragment<wmma::accumulator, 16, 16, 16, float> acc[2][NJ];
    #pragma unroll
    for (int i = 0; i < 2; i++)
        #pragma unroll
        for (int j = 0; j < NJ; j++) wmma::fill_fragment(acc[i][j], 0.f);

    #pragma unroll
    for (int k = 0; k < DIN; k += 16) {
        wmma::fragment<wmma::matrix_a, 16, 16, 16, __half, wmma::row_major> af[2];
        wmma::load_matrix_sync(af[0], &As[wr*32     ][k], SA);
        wmma::load_matrix_sync(af[1], &As[wr*32 + 16][k], SA);
        #pragma unroll
        for (int j = 0; j < NJ; j++) {
            wmma::fragment<wmma::matrix_b, 16, 16, 16, __half, wmma::row_major> bf;
            wmma::load_matrix_sync(bf, &Ws[k][wc*(NC/2) + j*16], SB);
            wmma::mma_sync(acc[0][j], af[0], bf, acc[0][j]);
            wmma::mma_sync(acc[1][j], af[1], bf, acc[1][j]);
        }
    }
    __syncthreads();                         // A tile dead; reuse as scratch

    // epilogue: frag -> smem -> fp16 global (stride NCOUT, cols >= NCOUT dropped)
    int r = lane >> 1, c = (lane & 1) * 8;
    #pragma unroll
    for (int i = 0; i < 2; i++) {
        #pragma unroll
        for (int j = 0; j < NJ; j++) {
            wmma::store_matrix_sync(&scr[wid][0][0], acc[i][j], 20, wmma::mem_row_major);
            __syncwarp();
            int gcol = wc*(NC/2) + j*16 + c;
            int grow = row0 + wr*32 + i*16 + r;
            if (gcol < NCOUT && grow < NN) {
                float* s = &scr[wid][r][c];
                __half2 h0 = __floats2half2_rn(s[0], s[1]);
                __half2 h1 = __floats2half2_rn(s[2], s[3]);
                __half2 h2 = __floats2half2_rn(s[4], s[5]);
                __half2 h3 = __floats2half2_rn(s[6], s[7]);
                __half* dst = g_h16 + (size_t)grow * NCOUT + gcol;
                uint2 o0; o0.x = *(unsigned*)&h0; o0.y = *(unsigned*)&h1;
                uint2 o1; o1.x = *(unsigned*)&h2; o1.y = *(unsigned*)&h3;
                ((uint2*)dst)[0] = o0;
                ((uint2*)dst)[1] = o1;
            }
            __syncwarp();
        }
    }
}

// ---------------- aggregation (D=128): fp16 gathers, fp32 accumulate ----------------
__device__ __forceinline__ void accf(float4& acc, uint2 u, float dv) {
    float2 f0 = __half22float2(*(__half2*)&u.x);
    float2 f1 = __half22float2(*(__half2*)&u.y);
    acc.x = fmaf(f0.x, dv, acc.x);
    acc.y = fmaf(f0.y, dv, acc.y);
    acc.z = fmaf(f1.x, dv, acc.z);
    acc.w = fmaf(f1.y, dv, acc.w);
}

__global__ void __launch_bounds__(256) aggregate_k(const float* __restrict__ bias) {
    int gw   = (blockIdx.x*blockDim.x + threadIdx.x) >> 5;
    int lane = threadIdx.x & 31;
    if (gw >= NN) return;

    const __half* H = g_h16;
    int co = lane * 4;
    float dvi = g_dinv[gw];

    float4 acc = make_float4(0.f, 0.f, 0.f, 0.f);
    accf(acc, *(const uint2*)(H + (size_t)gw * DH + co), dvi);   // self-loop

    int e   = g_rowptr[gw];
    int end = g_rowptr[gw + 1];
    for (; e + 3 < end; e += 4) {
        int s0 = g_srcs[e], s1 = g_srcs[e+1], s2 = g_srcs[e+2], s3 = g_srcs[e+3];
        float d0 = g_dinv[s0], d1 = g_dinv[s1], d2 = g_dinv[s2], d3 = g_dinv[s3];
        uint2 u0 = *(const uint2*)(H + (size_t)s0 * DH + co);
        uint2 u1 = *(const uint2*)(H + (size_t)s1 * DH + co);
        uint2 u2 = *(const uint2*)(H + (size_t)s2 * DH + co);
        uint2 u3 = *(const uint2*)(H + (size_t)s3 * DH + co);
        accf(acc, u0, d0); accf(acc, u1, d1);
        accf(acc, u2, d2); accf(acc, u3, d3);
    }
    for (; e < end; e++) {
        int s = g_srcs[e];
        accf(acc, *(const uint2*)(H + (size_t)s * DH + co), g_dinv[s]);
    }

    float4 bb = ((const float4*)bias)[lane];
    float ox = fmaxf(fmaf(acc.x, dvi, bb.x), 0.f);
    float oy = fmaxf(fmaf(acc.y, dvi, bb.y), 0.f);
    float oz = fmaxf(fmaf(acc.z, dvi, bb.z), 0.f);
    float ow = fmaxf(fmaf(acc.w, dvi, bb.w), 0.f);
    __half2 h0 = __floats2half2_rn(ox, oy);
    __half2 h1 = __floats2half2_rn(oz, ow);
    uint2 o; o.x = *(unsigned*)&h0; o.y = *(unsigned*)&h1;
    *(uint2*)(g_a16 + (size_t)gw * DH + co) = o;
}

// ---------------- final: aggregate(40) + bias + relu + log_softmax ----------------
__global__ void __launch_bounds__(256) agg40_softmax_k(const float* __restrict__ bias,
                                                       float* __restrict__ out) {
    int gw   = (blockIdx.x*blockDim.x + threadIdx.x) >> 5;
    int lane = threadIdx.x & 31;
    if (gw >= NN) return;
    const int NV = DOUTC / 4;               // 10 active lanes
    bool act = lane < NV;

    const __half* H = g_h16;
    int co = lane * 4;
    float dvi = g_dinv[gw];

    float4 o = make_float4(0.f, 0.f, 0.f, 0.f);
    if (act) {
        float4 acc = make_float4(0.f, 0.f, 0.f, 0.f);
        accf(acc, *(const uint2*)(H + (size_t)gw * DOUTC + co), dvi);
        int e   = g_rowptr[gw];
        int end = g_rowptr[gw + 1];
        for (; e + 3 < end; e += 4) {
            int s0 = g_srcs[e], s1 = g_srcs[e+1], s2 = g_srcs[e+2], s3 = g_srcs[e+3];
            float d0 = g_dinv[s0], d1 = g_dinv[s1], d2 = g_dinv[s2], d3 = g_dinv[s3];
            uint2 u0 = *(const uint2*)(H + (size_t)s0 * DOUTC + co);
            uint2 u1 = *(const uint2*)(H + (size_t)s1 * DOUTC + co);
            uint2 u2 = *(const uint2*)(H + (size_t)s2 * DOUTC + co);
            uint2 u3 = *(const uint2*)(H + (size_t)s3 * DOUTC + co);
            accf(acc, u0, d0); accf(acc, u1, d1);
            accf(acc, u2, d2); accf(acc, u3, d3);
        }
        for (; e < end; e++) {
            int s = g_srcs[e];
            accf(acc, *(const uint2*)(H + (size_t)s * DOUTC + co), g_dinv[s]);
        }
        float4 bb = ((const float4*)bias)[lane];
        o.x = fmaxf(fmaf(acc.x, dvi, bb.x), 0.f);
        o.y = fmaxf(fmaf(acc.y, dvi, bb.y), 0.f);
        o.z = fmaxf(fmaf(acc.z, dvi, bb.z), 0.f);
        o.w = fmaxf(fmaf(acc.w, dvi, bb.w), 0.f);
    }

    float m = act ? fmaxf(fmaxf(o.x, o.y), fmaxf(o.z, o.w)) : -CUDART_INF_F;
    #pragma unroll
    for (int off = 16; off; off >>= 1)
        m = fmaxf(m, __shfl_xor_sync(0xffffffffu, m, off));
    float s = act ? (__expf(o.x - m) + __expf(o.y - m) +
                     __expf(o.z - m) + __expf(o.w - m)) : 0.f;
    #pragma unroll
    for (int off = 16; off; off >>= 1)
        s += __shfl_xor_sync(0xffffffffu, s, off);
    float lse = m + __logf(s);

    if (act) {
        float4 r;
        r.x = o.x - lse; r.y = o.y - lse; r.z = o.z - lse; r.w = o.w - lse;
        ((float4*)(out + (size_t)gw * DOUTC))[lane] = r;
    }
}

// ---------------- launch ----------------
extern "C" void kernel_launch(void* const* d_in, const int* in_sizes, int n_in,
                              void* d_out, int out_size) {
    const float* x  = (const float*)d_in[0];
    const int*   ei = (const int*)d_in[1];      // int32: JAX x64 disabled
    const float* W0 = (const float*)d_in[2];
    const float* b0 = (const float*)d_in[3];
    const float* W1 = (const float*)d_in[4];
    const float* b1 = (const float*)d_in[5];
    const float* W2 = (const float*)d_in[6];
    const float* b2 = (const float*)d_in[7];
    float* out = (float*)d_out;

    __half *w0h, *w1h, *w2h;
    void* degp;
    cudaGetSymbolAddress((void**)&w0h, g_w0h);
    cudaGetSymbolAddress((void**)&w1h, g_w1h);
    cudaGetSymbolAddress((void**)&w2h, g_w2h);
    cudaGetSymbolAddress(&degp, g_deg);

    const int SM128 = 128*(DIN+8)*2 + DIN*(128+8)*2;   // 69632
    const int SM64  = 128*(DIN+8)*2 + DIN*(64+8)*2;    // 53248
    cudaFuncSetAttribute(gemm3_k<128,128>,
                         cudaFuncAttributeMaxDynamicSharedMemorySize, SM128);
    cudaFuncSetAttribute(gemm3_k<64,40>,
                         cudaFuncAttributeMaxDynamicSharedMemorySize, SM64);

    const int GB = NROWP / 128;             // 391 gemm blocks
    const int GA = (NN * 32 + 255) / 256;   // one warp per node

    cudaMemsetAsync(degp, 0, NN*sizeof(int));
    fused_pre_k <<<(PRE_TOT + 255)/256, 256>>>(x, ei, W0, W1, W2);  // 1
    scan1_k     <<<NB, 256>>>();                                    // 2
    scan23_k    <<<NB, 256>>>();                                    // 3
    gemm3_k<128, 128><<<GB, 256, SM128>>>(w0h);                     // 4 <- profiled
    sort_edges_k<<<(EE + 255)/256, 256>>>(ei);                      // 5
    aggregate_k <<<GA, 256>>>(b0);                                  // 6
    gemm3_k<128, 128><<<GB, 256, SM128>>>(w1h);                     // 7
    aggregate_k <<<GA, 256>>>(b1);                                  // 8
    gemm3_k<64, 40><<<GB, 256, SM64>>>(w2h);                        // 9
    agg40_softmax_k<<<GA, 256>>>(b2, out);                          // 10
}

// round 16
// speedup vs baseline: 2.7876x; 1.0584x over previous
#include <cuda_runtime.h>
#include <cuda_fp16.h>
#include <mma.h>
#include <math.h>
#include <math_constants.h>

using namespace nvcuda;

#define NN    50000
#define EE    800000
#define DIN   128
#define DH    128
#define DOUTC 40
#define NB    ((NN + 255) / 256)    // 196 scan blocks
#define NROWP 50048                 // 391 * 128, NN rounded up

// ---------------- device scratch (no allocs allowed) ----------------
__device__ __half g_a16[NROWP*DH];  // GEMM input (cvt(x) / aggregate output)
__device__ __half g_h16[NROWP*DH];  // GEMM output h = A @ W (fp16)
__device__ __half g_w0h[DIN*DH];
__device__ __half g_w1h[DH*DH];
__device__ __half g_w2h[DH*64];     // padded 40->64 cols
__device__ float  g_dinv[NN];
__device__ int    g_deg[NN];
__device__ int    g_rowptr[NN+1];
__device__ int    g_cursor[NN];
__device__ int    g_srcs[EE];       // edge srcs sorted by dst (CSR)
__device__ int    g_bsum[NB];

// ---------------- dense-side pre: cvt(x) + W->fp16 ----------------
#define CVT_N   (NN*DH/4)                       // 1,600,000 float4
#define TDUP    (DIN*DH + DH*DH + DH*64)        // 40,960
#define PREA_TOT (CVT_N + TDUP)

__global__ void pre_a_k(const float* __restrict__ x,
                        const float* __restrict__ W0,
                        const float* __restrict__ W1,
                        const float* __restrict__ W2) {
    int idx = blockIdx.x*blockDim.x + threadIdx.x;
    if (idx < CVT_N) {
        float4 v = ((const float4*)x)[idx];
        __half2 h0 = __floats2half2_rn(v.x, v.y);
        __half2 h1 = __floats2half2_rn(v.z, v.w);
        uint2 o; o.x = *(unsigned*)&h0; o.y = *(unsigned*)&h1;
        ((uint2*)g_a16)[idx] = o;
    } else if (idx < PREA_TOT) {
        int j = idx - CVT_N;
        const int T0 = DIN*DH, T1 = T0 + DH*DH;
        if (j < T0) {
            g_w0h[j] = __float2half(W0[j]);
        } else if (j < T1) {
            g_w1h[j - T0] = __float2half(W1[j - T0]);
        } else {
            int jj = j - T1;
            int k = jj / 64, c = jj % 64;
            g_w2h[jj] = __float2half((c < DOUTC) ? W2[k*DOUTC + c] : 0.f);
        }
    }
}

// ---------------- edge-side pre ----------------
// edge_index is int32 (JAX x64 disabled): [0:EE)=src, [EE:2EE)=dst
__global__ void count_deg_k(const int* __restrict__ ei) {
    int e = blockIdx.x*blockDim.x + threadIdx.x;
    if (e < EE) {
        unsigned d = (unsigned)ei[EE + e];
        if (d < NN) atomicAdd(&g_deg[d], 1);
    }
}

__global__ void scan1_k() {
    __shared__ int sd[256];
    int tid = threadIdx.x;
    int i = blockIdx.x*256 + tid;
    int d = (i < NN) ? g_deg[i] : 0;
    if (i < NN) g_dinv[i] = rsqrtf((float)(d + 1));   // +1 self-loop
    sd[tid] = d;
    __syncthreads();
    for (int off = 128; off; off >>= 1) {
        if (tid < off) sd[tid] += sd[tid + off];
        __syncthreads();
    }
    if (tid == 0) g_bsum[blockIdx.x] = sd[0];
}

__global__ void scan23_k() {
    __shared__ int sd[256];
    int b = blockIdx.x, tid = threadIdx.x;

    int p = 0;
    for (int j = tid; j < b; j += 256) p += g_bsum[j];
    sd[tid] = p;
    __syncthreads();
    for (int off = 128; off; off >>= 1) {
        if (tid < off) sd[tid] += sd[tid + off];
        __syncthreads();
    }
    int base0 = sd[0];
    __syncthreads();

    int i = b*256 + tid;
    int d = (i < NN) ? g_deg[i] : 0;
    sd[tid] = d;
    __syncthreads();
    for (int off = 1; off < 256; off <<= 1) {
        int t = (tid >= off) ? sd[tid - off] : 0;
        __syncthreads();
        sd[tid] += t;
        __syncthreads();
    }
    if (i < NN) {
        int base = base0 + sd[tid] - d;   // exclusive
        g_rowptr[i] = base;
        g_cursor[i] = base;
    }
    if (b == NB-1 && tid == 255) g_rowptr[NN] = base0 + sd[255];
}

__global__ void sort_edges_k(const int* __restrict__ ei) {
    int e = blockIdx.x*blockDim.x + threadIdx.x;
    if (e < EE) {
        unsigned d = (unsigned)ei[EE + e];
        unsigned s = (unsigned)ei[e];
        if (d < NN && s < NN) {
            int pos = atomicAdd(&g_cursor[d], 1);
            if (pos < EE) g_srcs[pos] = (int)s;
        }
    }
}

// ---------------- GEMM v3: g_h16 = g_a16 @ W  (wmma fp16, fp32 accum) ----------------
// 256 threads = 8 warps; block tile = 128 rows x NC cols.
// Warp tile = 32 rows x NC/2 cols. A and W staged in padded smem (conflict-free LDSM).
template<int NC, int NCOUT>
__global__ void __launch_bounds__(256) gemm3_k(const __half* __restrict__ B) {
    const int SA = DIN + 8;                  // 136
    const int SB = NC + 8;                   // 136 / 72
    const int NJ = NC / 32;                  // col frags per warp: 4 / 2
    extern __shared__ char smraw[];
    __half (*As)[SA] = (__half(*)[SA])smraw;                       // 128*272B
    __half (*Ws)[SB] = (__half(*)[SB])(smraw + 128*SA*2);
    float  (*scr)[16][20] = (float(*)[16][20])smraw;               // reused post-sync

    int tid = threadIdx.x, wid = tid >> 5, lane = tid & 31;
    int wr = wid >> 1, wc = wid & 1;
    int row0 = blockIdx.x * 128;

    // stage W (uint4 = 8 halves)
    const int WV = DIN * NC / 8;
    #pragma unroll
    for (int i = tid; i < WV; i += 256) {
        int r = i / (NC/8), c = i % (NC/8);
        ((uint4*)&Ws[r][0])[c] = ((const uint4*)B)[i];
    }
    // stage A: 128 rows x 16 uint4 (rows >= NN read zero padding of g_a16)
    #pragma unroll
    for (int i = tid; i < 128*16; i += 256) {
        int r = i >> 4, c = i & 15;
        ((uint4*)&As[r][0])[c] =
            ((const uint4*)(g_a16 + (size_t)(row0 + r) * DIN))[c];
    }
    __syncthreads();

    wmma::fragment<wmma::accumulator, 16, 16, 16, float> acc[2][NJ];
    #pragma unroll
    for (int i = 0; i < 2; i++)
        #pragma unroll
        for (int j = 0; j < NJ; j++) wmma::fill_fragment(acc[i][j], 0.f);

    #pragma unroll
    for (int k = 0; k < DIN; k += 16) {
        wmma::fragment<wmma::matrix_a, 16, 16, 16, __half, wmma::row_major> af[2];
        wmma::load_matrix_sync(af[0], &As[wr*32     ][k], SA);
        wmma::load_matrix_sync(af[1], &As[wr*32 + 16][k], SA);
        #pragma unroll
        for (int j = 0; j < NJ; j++) {
            wmma::fragment<wmma::matrix_b, 16, 16, 16, __half, wmma::row_major> bf;
            wmma::load_matrix_sync(bf, &Ws[k][wc*(NC/2) + j*16], SB);
            wmma::mma_sync(acc[0][j], af[0], bf, acc[0][j]);
            wmma::mma_sync(acc[1][j], af[1], bf, acc[1][j]);
        }
    }
    __syncthreads();                         // A tile dead; reuse as scratch

    // epilogue: frag -> smem -> fp16 global (stride NCOUT, cols >= NCOUT dropped)
    int r = lane >> 1, c = (lane & 1) * 8;
    #pragma unroll
    for (int i = 0; i < 2; i++) {
        #pragma unroll
        for (int j = 0; j < NJ; j++) {
            wmma::store_matrix_sync(&scr[wid][0][0], acc[i][j], 20, wmma::mem_row_major);
            __syncwarp();
            int gcol = wc*(NC/2) + j*16 + c;
            int grow = row0 + wr*32 + i*16 + r;
            if (gcol < NCOUT && grow < NN) {
                float* s = &scr[wid][r][c];
                __half2 h0 = __floats2half2_rn(s[0], s[1]);
                __half2 h1 = __floats2half2_rn(s[2], s[3]);
                __half2 h2 = __floats2half2_rn(s[4], s[5]);
                __half2 h3 = __floats2half2_rn(s[6], s[7]);
                __half* dst = g_h16 + (size_t)grow * NCOUT + gcol;
                uint2 o0; o0.x = *(unsigned*)&h0; o0.y = *(unsigned*)&h1;
                uint2 o1; o1.x = *(unsigned*)&h2; o1.y = *(unsigned*)&h3;
                ((uint2*)dst)[0] = o0;
                ((uint2*)dst)[1] = o1;
            }
            __syncwarp();
        }
    }
}

// ---------------- aggregation (D=128): fp16 gathers, fp32 accumulate ----------------
__device__ __forceinline__ void accf(float4& acc, uint2 u, float dv) {
    float2 f0 = __half22float2(*(__half2*)&u.x);
    float2 f1 = __half22float2(*(__half2*)&u.y);
    acc.x = fmaf(f0.x, dv, acc.x);
    acc.y = fmaf(f0.y, dv, acc.y);
    acc.z = fmaf(f1.x, dv, acc.z);
    acc.w = fmaf(f1.y, dv, acc.w);
}

__global__ void __launch_bounds__(256) aggregate_k(const float* __restrict__ bias) {
    int gw   = (blockIdx.x*blockDim.x + threadIdx.x) >> 5;
    int lane = threadIdx.x & 31;
    if (gw >= NN) return;

    const __half* H = g_h16;
    int co = lane * 4;
    float dvi = g_dinv[gw];

    float4 acc = make_float4(0.f, 0.f, 0.f, 0.f);
    accf(acc, *(const uint2*)(H + (size_t)gw * DH + co), dvi);   // self-loop

    int e   = g_rowptr[gw];
    int end = g_rowptr[gw + 1];
    for (; e + 3 < end; e += 4) {
        int s0 = g_srcs[e], s1 = g_srcs[e+1], s2 = g_srcs[e+2], s3 = g_srcs[e+3];
        float d0 = g_dinv[s0], d1 = g_dinv[s1], d2 = g_dinv[s2], d3 = g_dinv[s3];
        uint2 u0 = *(const uint2*)(H + (size_t)s0 * DH + co);
        uint2 u1 = *(const uint2*)(H + (size_t)s1 * DH + co);
        uint2 u2 = *(const uint2*)(H + (size_t)s2 * DH + co);
        uint2 u3 = *(const uint2*)(H + (size_t)s3 * DH + co);
        accf(acc, u0, d0); accf(acc, u1, d1);
        accf(acc, u2, d2); accf(acc, u3, d3);
    }
    for (; e < end; e++) {
        int s = g_srcs[e];
        accf(acc, *(const uint2*)(H + (size_t)s * DH + co), g_dinv[s]);
    }

    float4 bb = ((const float4*)bias)[lane];
    float ox = fmaxf(fmaf(acc.x, dvi, bb.x), 0.f);
    float oy = fmaxf(fmaf(acc.y, dvi, bb.y), 0.f);
    float oz = fmaxf(fmaf(acc.z, dvi, bb.z), 0.f);
    float ow = fmaxf(fmaf(acc.w, dvi, bb.w), 0.f);
    __half2 h0 = __floats2half2_rn(ox, oy);
    __half2 h1 = __floats2half2_rn(oz, ow);
    uint2 o; o.x = *(unsigned*)&h0; o.y = *(unsigned*)&h1;
    *(uint2*)(g_a16 + (size_t)gw * DH + co) = o;
}

// ---------------- final: aggregate(40) + bias + relu + log_softmax ----------------
__global__ void __launch_bounds__(256) agg40_softmax_k(const float* __restrict__ bias,
                                                       float* __restrict__ out) {
    int gw   = (blockIdx.x*blockDim.x + threadIdx.x) >> 5;
    int lane = threadIdx.x & 31;
    if (gw >= NN) return;
    const int NV = DOUTC / 4;               // 10 active lanes
    bool act = lane < NV;

    const __half* H = g_h16;
    int co = lane * 4;
    float dvi = g_dinv[gw];

    float4 o = make_float4(0.f, 0.f, 0.f, 0.f);
    if (act) {
        float4 acc = make_float4(0.f, 0.f, 0.f, 0.f);
        accf(acc, *(const uint2*)(H + (size_t)gw * DOUTC + co), dvi);
        int e   = g_rowptr[gw];
        int end = g_rowptr[gw + 1];
        for (; e + 3 < end; e += 4) {
            int s0 = g_srcs[e], s1 = g_srcs[e+1], s2 = g_srcs[e+2], s3 = g_srcs[e+3];
            float d0 = g_dinv[s0], d1 = g_dinv[s1], d2 = g_dinv[s2], d3 = g_dinv[s3];
            uint2 u0 = *(const uint2*)(H + (size_t)s0 * DOUTC + co);
            uint2 u1 = *(const uint2*)(H + (size_t)s1 * DOUTC + co);
            uint2 u2 = *(const uint2*)(H + (size_t)s2 * DOUTC + co);
            uint2 u3 = *(const uint2*)(H + (size_t)s3 * DOUTC + co);
            accf(acc, u0, d0); accf(acc, u1, d1);
            accf(acc, u2, d2); accf(acc, u3, d3);
        }
        for (; e < end; e++) {
            int s = g_srcs[e];
            accf(acc, *(const uint2*)(H + (size_t)s * DOUTC + co), g_dinv[s]);
        }
        float4 bb = ((const float4*)bias)[lane];
        o.x = fmaxf(fmaf(acc.x, dvi, bb.x), 0.f);
        o.y = fmaxf(fmaf(acc.y, dvi, bb.y), 0.f);
        o.z = fmaxf(fmaf(acc.z, dvi, bb.z), 0.f);
        o.w = fmaxf(fmaf(acc.w, dvi, bb.w), 0.f);
    }

    float m = act ? fmaxf(fmaxf(o.x, o.y), fmaxf(o.z, o.w)) : -CUDART_INF_F;
    #pragma unroll
    for (int off = 16; off; off >>= 1)
        m = fmaxf(m, __shfl_xor_sync(0xffffffffu, m, off));
    float s = act ? (__expf(o.x - m) + __expf(o.y - m) +
                     __expf(o.z - m) + __expf(o.w - m)) : 0.f;
    #pragma unroll
    for (int off = 16; off; off >>= 1)
        s += __shfl_xor_sync(0xffffffffu, s, off);
    float lse = m + __logf(s);

    if (act) {
        float4 r;
        r.x = o.x - lse; r.y = o.y - lse; r.z = o.z - lse; r.w = o.w - lse;
        ((float4*)(out + (size_t)gw * DOUTC))[lane] = r;
    }
}

// ---------------- launch (forked-stream capture: dense || edge pipelines) ------
extern "C" void kernel_launch(void* const* d_in, const int* in_sizes, int n_in,
                              void* d_out, int out_size) {
    const float* x  = (const float*)d_in[0];
    const int*   ei = (const int*)d_in[1];      // int32: JAX x64 disabled
    const float* W0 = (const float*)d_in[2];
    const float* b0 = (const float*)d_in[3];
    const float* W1 = (const float*)d_in[4];
    const float* b1 = (const float*)d_in[5];
    const float* W2 = (const float*)d_in[6];
    const float* b2 = (const float*)d_in[7];
    float* out = (float*)d_out;

    __half *w0h, *w1h, *w2h;
    void* degp;
    cudaGetSymbolAddress((void**)&w0h, g_w0h);
    cudaGetSymbolAddress((void**)&w1h, g_w1h);
    cudaGetSymbolAddress((void**)&w2h, g_w2h);
    cudaGetSymbolAddress(&degp, g_deg);

    const int SM128 = 128*(DIN+8)*2 + DIN*(128+8)*2;   // 69632
    const int SM64  = 128*(DIN+8)*2 + DIN*(64+8)*2;    // 53248
    cudaFuncSetAttribute(gemm3_k<128,128>,
                         cudaFuncAttributeMaxDynamicSharedMemorySize, SM128);
    cudaFuncSetAttribute(gemm3_k<64,40>,
                         cudaFuncAttributeMaxDynamicSharedMemorySize, SM64);

    const int GB = NROWP / 128;             // 391 gemm blocks
    const int GA = (NN * 32 + 255) / 256;   // one warp per node

    cudaStream_t s2;
    cudaEvent_t evFork, evJoin;
    cudaStreamCreateWithFlags(&s2, cudaStreamNonBlocking);
    cudaEventCreateWithFlags(&evFork, cudaEventDisableTiming);
    cudaEventCreateWithFlags(&evJoin, cudaEventDisableTiming);

    // main stream: zero deg, then fork
    cudaMemsetAsync(degp, 0, NN*sizeof(int));
    cudaEventRecord(evFork, 0);
    cudaStreamWaitEvent(s2, evFork, 0);

    // edge pipeline (stream s2): histogram -> scans -> CSR scatter
    count_deg_k <<<(EE + 255)/256, 256, 0, s2>>>(ei);
    scan1_k     <<<NB, 256, 0, s2>>>();
    scan23_k    <<<NB, 256, 0, s2>>>();
    sort_edges_k<<<(EE + 255)/256, 256, 0, s2>>>(ei);
    cudaEventRecord(evJoin, s2);

    // dense pipeline (main stream): cvt + W convert -> gemm0
    pre_a_k<<<(PREA_TOT + 255)/256, 256>>>(x, W0, W1, W2);
    gemm3_k<128, 128><<<GB, 256, SM128>>>(w0h);

    // join: aggregate needs h (main), CSR + dinv (s2)
    cudaStreamWaitEvent(0, evJoin, 0);

    aggregate_k <<<GA, 256>>>(b0);
    gemm3_k<128, 128><<<GB, 256, SM128>>>(w1h);
    aggregate_k <<<GA, 256>>>(b1);
    gemm3_k<64, 40><<<GB, 256, SM64>>>(w2h);
    agg40_softmax_k<<<GA, 256>>>(b2, out);

    cudaEventDestroy(evFork);
    cudaEventDestroy(evJoin);
    cudaStreamDestroy(s2);
}